// round 3
// baseline (speedup 1.0000x reference)
#include <cuda_runtime.h>
#include <math.h>

#define NOP 20000
#define NMM 500
#define DD  256
#define HH  8
#define DHD 32
#define TDE 16
#define EE  200000

// ---------------- scratch (static device globals; no allocation) ----------------
__device__ float g_xw[NOP * DD];        // temporally-updated x_op
__device__ float g_k_op[NOP * DD];
__device__ float g_q_op[NOP * DD];
__device__ float g_v_op[NOP * DD];
__device__ float g_k_m[NMM * DD];
__device__ float g_q_m[NMM * DD];
__device__ float g_v_m[NMM * DD];
__device__ float g_KT[NOP * DD];        // per-edge-type transformed keys (reused)
__device__ float g_VT[NOP * DD];        // per-edge-type transformed values (reused)
__device__ float g_expa[EE * HH];
__device__ float g_denom[NOP * HH];
__device__ float g_acc_op[NOP * DD];
__device__ float g_acc_m[NMM * DD];

__device__ __forceinline__ float gelu_exact(float x) {
    return 0.5f * x * (1.0f + erff(x * 0.70710678118654752f));
}

// ---------------- temporal encoding: one warp per edge ----------------
__global__ void temporal_kernel(const float* __restrict__ delta_t,
                                const int* __restrict__ ei_src,
                                const float* __restrict__ Wt,
                                const float* __restrict__ bt,
                                const float* __restrict__ ln_g,
                                const float* __restrict__ ln_b)
{
    __shared__ float Wts[TDE * DD];   // transposed: Wts[i*DD + j] = Wt[j*TDE + i]
    __shared__ float bts[DD], gs[DD], bs[DD];
    for (int idx = threadIdx.x; idx < DD * TDE; idx += blockDim.x) {
        int j = idx / TDE, i = idx % TDE;
        Wts[i * DD + j] = Wt[idx];
    }
    for (int idx = threadIdx.x; idx < DD; idx += blockDim.x) {
        bts[idx] = bt[idx]; gs[idx] = ln_g[idx]; bs[idx] = ln_b[idx];
    }
    __syncthreads();

    int w = (int)((blockIdx.x * blockDim.x + threadIdx.x) >> 5);
    int lane = threadIdx.x & 31;
    if (w >= EE) return;

    float dt = delta_t[w];
    int src = ei_src[w];

    float sn[8], cn[8];
    #pragma unroll
    for (int m = 0; m < 8; m++) {
        // freq = 1000^{-m/8}
        float freq = exp2f(-(float)m * (9.965784284662087f / 8.0f));
        sincosf(dt * freq, &sn[m], &cn[m]);
    }

    float pt[8];
    float lsum = 0.0f;
    #pragma unroll
    for (int jj = 0; jj < 8; jj++) {
        int j = lane + jj * 32;
        float s = bts[j];
        #pragma unroll
        for (int m = 0; m < 8; m++) {
            s += sn[m] * Wts[(2 * m) * DD + j] + cn[m] * Wts[(2 * m + 1) * DD + j];
        }
        pt[jj] = s;
        lsum += s;
    }
    #pragma unroll
    for (int o = 16; o; o >>= 1) lsum += __shfl_xor_sync(0xffffffffu, lsum, o);
    float mu = lsum * (1.0f / 256.0f);

    float lvar = 0.0f;
    #pragma unroll
    for (int jj = 0; jj < 8; jj++) { float d = pt[jj] - mu; lvar += d * d; }
    #pragma unroll
    for (int o = 16; o; o >>= 1) lvar += __shfl_xor_sync(0xffffffffu, lvar, o);
    float rstd = rsqrtf(lvar * (1.0f / 256.0f) + 1e-5f);

    #pragma unroll
    for (int jj = 0; jj < 8; jj++) {
        int j = lane + jj * 32;
        float y = (pt[jj] - mu) * rstd * gs[j] + bs[j];
        atomicAdd(&g_xw[(size_t)src * DD + j], y);
    }
}

// ---------------- generic C = A(N,256) * W(256,256)^T + b, 128x128x8 tile ----------------
// FUSE: gelu applied to A on load; epilogue does gated skip and writes final output.
template <bool FUSE>
__global__ void gemm128(const float* __restrict__ A, const float* __restrict__ W,
                        const float* __restrict__ bias, float* __restrict__ C, int N,
                        const float* __restrict__ xsrc, const float* __restrict__ skipv)
{
    __shared__ float As[8][128];
    __shared__ float Bs[8][128];

    int tid = threadIdx.x;
    int tx = tid & 15;    // column octet
    int ty = tid >> 4;    // row octet
    int rowBase = blockIdx.x * 128;
    int colBase = blockIdx.y * 128;

    float acc[8][8];
    #pragma unroll
    for (int i = 0; i < 8; i++)
        #pragma unroll
        for (int j = 0; j < 8; j++) acc[i][j] = 0.0f;

    int ldIdx = tid * 4;
    int lr = ldIdx >> 3;   // 0..127
    int lk = ldIdx & 7;    // 0 or 4

    for (int kt = 0; kt < 256; kt += 8) {
        float4 av = make_float4(0.f, 0.f, 0.f, 0.f);
        int gr = rowBase + lr;
        if (gr < N) av = *(const float4*)(A + (size_t)gr * 256 + kt + lk);
        if (FUSE) {
            av.x = gelu_exact(av.x); av.y = gelu_exact(av.y);
            av.z = gelu_exact(av.z); av.w = gelu_exact(av.w);
        }
        As[lk + 0][lr] = av.x; As[lk + 1][lr] = av.y;
        As[lk + 2][lr] = av.z; As[lk + 3][lr] = av.w;

        int gc = colBase + lr;  // always < 256
        float4 bv = *(const float4*)(W + (size_t)gc * 256 + kt + lk);
        Bs[lk + 0][lr] = bv.x; Bs[lk + 1][lr] = bv.y;
        Bs[lk + 2][lr] = bv.z; Bs[lk + 3][lr] = bv.w;
        __syncthreads();

        #pragma unroll
        for (int kk = 0; kk < 8; kk++) {
            float a[8], b[8];
            *(float4*)(a)     = *(const float4*)&As[kk][ty * 8];
            *(float4*)(a + 4) = *(const float4*)&As[kk][ty * 8 + 4];
            *(float4*)(b)     = *(const float4*)&Bs[kk][tx * 8];
            *(float4*)(b + 4) = *(const float4*)&Bs[kk][tx * 8 + 4];
            #pragma unroll
            for (int i = 0; i < 8; i++)
                #pragma unroll
                for (int j = 0; j < 8; j++) acc[i][j] += a[i] * b[j];
        }
        __syncthreads();
    }

    float sa = 0.0f;
    if (FUSE) sa = 1.0f / (1.0f + expf(-skipv[0]));

    #pragma unroll
    for (int i = 0; i < 8; i++) {
        int r = rowBase + ty * 8 + i;
        if (r >= N) continue;
        #pragma unroll
        for (int j = 0; j < 8; j++) {
            int c = colBase + tx * 8 + j;
            float o = acc[i][j] + bias[c];
            if (FUSE) {
                C[(size_t)r * 256 + c] = sa * o + (1.0f - sa) * xsrc[(size_t)r * 256 + c];
            } else {
                C[(size_t)r * 256 + c] = o;
            }
        }
    }
}

// ---------------- per-node relation transform: KT = k @ a_rel[e], VT = v @ m_rel[e] ----------------
// grid: (ceil(N/64), 8 heads); block 256 threads = 8 warps, each warp does 8 nodes (fixed head).
__global__ void rel_transform(const float* __restrict__ ktab, const float* __restrict__ vtab,
                              const float* __restrict__ arel, const float* __restrict__ mrel,
                              float* __restrict__ KT, float* __restrict__ VT, int N)
{
    int h = blockIdx.y;
    __shared__ float a_s[32 * 32], m_s[32 * 32];
    for (int i = threadIdx.x; i < 1024; i += 256) {
        a_s[i] = arel[h * 1024 + i];
        m_s[i] = mrel[h * 1024 + i];
    }
    __syncthreads();

    int warp = threadIdx.x >> 5, lane = threadIdx.x & 31;
    int n = blockIdx.x * 64 + warp * 8;
    #pragma unroll 1
    for (int t = 0; t < 8; t++, n++) {
        if (n >= N) break;
        float kv = ktab[(size_t)n * 256 + h * 32 + lane];
        float vv = vtab[(size_t)n * 256 + h * 32 + lane];
        float sk = 0.0f, sv = 0.0f;
        #pragma unroll
        for (int f = 0; f < 32; f++) {
            float kf = __shfl_sync(0xffffffffu, kv, f);
            float vf = __shfl_sync(0xffffffffu, vv, f);
            sk += kf * a_s[f * 32 + lane];
            sv += vf * m_s[f * 32 + lane];
        }
        KT[(size_t)n * 256 + h * 32 + lane] = sk;
        VT[(size_t)n * 256 + h * 32 + lane] = sv;
    }
}

// ---------------- attention pass 1: expa + denom (max-free softmax) ----------------
__global__ void attn_score(const int* __restrict__ ei,
                           const float* __restrict__ qtab,
                           const float* __restrict__ prel,
                           float* __restrict__ expa, float* __restrict__ denom)
{
    int w = (int)((blockIdx.x * blockDim.x + threadIdx.x) >> 5);
    int lane = threadIdx.x & 31;
    if (w >= EE) return;
    int src = ei[w];
    int dst = ei[EE + w];

    const float4* qp = (const float4*)(qtab + (size_t)dst * 256);
    const float4* kp = (const float4*)(g_KT + (size_t)src * 256);
    float4 q0 = qp[lane * 2], q1 = qp[lane * 2 + 1];
    float4 k0 = kp[lane * 2], k1 = kp[lane * 2 + 1];
    float s = q0.x * k0.x + q0.y * k0.y + q0.z * k0.z + q0.w * k0.w
            + q1.x * k1.x + q1.y * k1.y + q1.z * k1.z + q1.w * k1.w;
    s += __shfl_xor_sync(0xffffffffu, s, 1);
    s += __shfl_xor_sync(0xffffffffu, s, 2);
    int h = lane >> 2;
    if ((lane & 3) == 0) {
        float alpha = s * prel[h] * 0.17677669529663687f;  // 1/sqrt(32)
        float ev = expf(alpha);
        expa[(size_t)w * 8 + h] = ev;
        atomicAdd(&denom[(size_t)dst * 8 + h], ev);
    }
}

// ---------------- attention pass 2: weighted scatter of V_e ----------------
__global__ void attn_apply(const int* __restrict__ ei,
                           const float* __restrict__ expa,
                           const float* __restrict__ denom,
                           float* __restrict__ acc)
{
    int w = (int)((blockIdx.x * blockDim.x + threadIdx.x) >> 5);
    int lane = threadIdx.x & 31;
    if (w >= EE) return;
    int src = ei[w];
    int dst = ei[EE + w];
    int h = lane >> 2;
    float wgt = expa[(size_t)w * 8 + h] / denom[(size_t)dst * 8 + h];

    const float4* vp = (const float4*)(g_VT + (size_t)src * 256);
    float4 v0 = vp[lane * 2], v1 = vp[lane * 2 + 1];
    float* ap = acc + (size_t)dst * 256 + lane * 8;
    atomicAdd(ap + 0, v0.x * wgt);
    atomicAdd(ap + 1, v0.y * wgt);
    atomicAdd(ap + 2, v0.z * wgt);
    atomicAdd(ap + 3, v0.w * wgt);
    atomicAdd(ap + 4, v1.x * wgt);
    atomicAdd(ap + 5, v1.y * wgt);
    atomicAdd(ap + 6, v1.z * wgt);
    atomicAdd(ap + 7, v1.w * wgt);
}

// ---------------- host side ----------------
static float* symaddr(const void* sym) {
    void* p = nullptr;
    cudaGetSymbolAddress(&p, sym);
    return (float*)p;
}

extern "C" void kernel_launch(void* const* d_in, const int* in_sizes, int n_in,
                              void* d_out, int out_size)
{
    const float* x_op    = (const float*)d_in[0];
    const float* x_m     = (const float*)d_in[1];
    const float* delta_t = (const float*)d_in[2];
    const int*   ei[4]   = {(const int*)d_in[3], (const int*)d_in[4],
                            (const int*)d_in[5], (const int*)d_in[6]};
    const float* Wt   = (const float*)d_in[7];
    const float* bt   = (const float*)d_in[8];
    const float* ln_g = (const float*)d_in[9];
    const float* ln_b = (const float*)d_in[10];
    const float* Wk   = (const float*)d_in[11];
    const float* bk   = (const float*)d_in[12];
    const float* Wq   = (const float*)d_in[13];
    const float* bq   = (const float*)d_in[14];
    const float* Wv   = (const float*)d_in[15];
    const float* bv   = (const float*)d_in[16];
    const float* Wa   = (const float*)d_in[17];
    const float* ba   = (const float*)d_in[18];
    const float* skip = (const float*)d_in[19];
    const float* a_rel = (const float*)d_in[20];
    const float* m_rel = (const float*)d_in[21];
    const float* p_rel = (const float*)d_in[22];
    float* out = (float*)d_out;

    float* xw    = symaddr(g_xw);
    float* k_op  = symaddr(g_k_op);
    float* q_op  = symaddr(g_q_op);
    float* v_op  = symaddr(g_v_op);
    float* k_m   = symaddr(g_k_m);
    float* q_m   = symaddr(g_q_m);
    float* v_m   = symaddr(g_v_m);
    float* KT    = symaddr(g_KT);
    float* VT    = symaddr(g_VT);
    float* expa  = symaddr(g_expa);
    float* denom = symaddr(g_denom);
    float* acc_op = symaddr(g_acc_op);
    float* acc_m  = symaddr(g_acc_m);

    cudaMemcpyAsync(xw, x_op, (size_t)NOP * DD * sizeof(float), cudaMemcpyDeviceToDevice);
    cudaMemsetAsync(acc_op, 0, (size_t)NOP * DD * sizeof(float));
    cudaMemsetAsync(acc_m, 0, (size_t)NMM * DD * sizeof(float));

    // temporal encoding: warp per edge on ei_mp, scatter-add into xw
    temporal_kernel<<<(EE + 7) / 8, 256>>>(delta_t, ei[0], Wt, bt, ln_g, ln_b);

    // k/q/v projections
    dim3 gOp((NOP + 127) / 128, 2);
    dim3 gM((NMM + 127) / 128, 2);
    gemm128<false><<<gOp, 256>>>(xw, Wk, bk, k_op, NOP, nullptr, nullptr);
    gemm128<false><<<gOp, 256>>>(xw, Wq, bq, q_op, NOP, nullptr, nullptr);
    gemm128<false><<<gOp, 256>>>(xw, Wv, bv, v_op, NOP, nullptr, nullptr);
    gemm128<false><<<gM, 256>>>(x_m, Wk + DD * DD, bk + DD, k_m, NMM, nullptr, nullptr);
    gemm128<false><<<gM, 256>>>(x_m, Wq + DD * DD, bq + DD, q_m, NMM, nullptr, nullptr);
    gemm128<false><<<gM, 256>>>(x_m, Wv + DD * DD, bv + DD, v_m, NMM, nullptr, nullptr);

    const int stype[4] = {0, 0, 0, 1};
    const int dtype[4] = {0, 0, 1, 0};
    for (int e = 0; e < 4; e++) {
        const float* ktab = stype[e] ? k_m : k_op;
        const float* vtab = stype[e] ? v_m : v_op;
        const float* qtab = dtype[e] ? q_m : q_op;
        int Ns = stype[e] ? NMM : NOP;
        int Nd = dtype[e] ? NMM : NOP;
        float* acc = dtype[e] ? acc_m : acc_op;

        dim3 gt((Ns + 63) / 64, 8);
        rel_transform<<<gt, 256>>>(ktab, vtab,
                                   a_rel + (size_t)e * HH * DHD * DHD,
                                   m_rel + (size_t)e * HH * DHD * DHD,
                                   KT, VT, Ns);
        cudaMemsetAsync(denom, 0, (size_t)Nd * HH * sizeof(float));
        attn_score<<<(EE + 7) / 8, 256>>>(ei[e], qtab, p_rel + (size_t)e * HH, expa, denom);
        attn_apply<<<(EE + 7) / 8, 256>>>(ei[e], expa, denom, acc);
    }

    // final: res = sigmoid(skip) * (gelu(acc) @ Wa^T + ba) + (1 - sigmoid(skip)) * x
    gemm128<true><<<gOp, 256>>>(acc_op, Wa, ba, out, NOP, xw, skip);
    gemm128<true><<<gM, 256>>>(acc_m, Wa + DD * DD, ba + DD, out + (size_t)NOP * DD, NMM, x_m, skip + 1);
}

// round 4
// speedup vs baseline: 1.4757x; 1.4757x over previous
#include <cuda_runtime.h>
#include <math.h>

#define NOP 20000
#define NMM 500
#define DD  256
#define HH  8
#define DHD 32
#define TDE 16
#define EE  200000

// ---------------- scratch (static device globals; no allocation) ----------------
__device__ float g_xw[NOP * DD];        // temporally-updated x_op
__device__ float g_k_op[NOP * DD];
__device__ float g_q_op[NOP * DD];
__device__ float g_v_op[NOP * DD];
__device__ float g_k_m[NMM * DD];
__device__ float g_q_m[NMM * DD];
__device__ float g_v_m[NMM * DD];
__device__ float g_KT[NOP * DD];        // per-edge-type transformed keys (reused)
__device__ float g_VT[NOP * DD];        // per-edge-type transformed values (reused)
__device__ float g_num[NOP * DD];       // unnormalized softmax numerator (zeroed by normalize)
__device__ float g_denom[NOP * HH];
__device__ float g_acc_op[NOP * DD];
__device__ float g_acc_m[NMM * DD];

__device__ __forceinline__ float gelu_exact(float x) {
    return 0.5f * x * (1.0f + erff(x * 0.70710678118654752f));
}

// vector reduction-add to global memory (sm_90+). 16B-aligned address required.
__device__ __forceinline__ void red_add_v4(float* p, float a, float b, float c, float d) {
    asm volatile("red.global.add.v4.f32 [%0], {%1, %2, %3, %4};"
                 :: "l"(p), "f"(a), "f"(b), "f"(c), "f"(d) : "memory");
}

// ---------------- temporal encoding: one warp per edge ----------------
__global__ void temporal_kernel(const float* __restrict__ delta_t,
                                const int* __restrict__ ei_src,
                                const float* __restrict__ Wt,
                                const float* __restrict__ bt,
                                const float* __restrict__ ln_g,
                                const float* __restrict__ ln_b)
{
    __shared__ float Wts[TDE * DD];   // transposed: Wts[i*DD + j] = Wt[j*TDE + i]
    __shared__ float bts[DD], gs[DD], bs[DD];
    __shared__ float tr[8][DD];       // per-warp transpose staging
    for (int idx = threadIdx.x; idx < DD * TDE; idx += blockDim.x) {
        int j = idx / TDE, i = idx % TDE;
        Wts[i * DD + j] = Wt[idx];
    }
    for (int idx = threadIdx.x; idx < DD; idx += blockDim.x) {
        bts[idx] = bt[idx]; gs[idx] = ln_g[idx]; bs[idx] = ln_b[idx];
    }
    __syncthreads();

    int w = (int)((blockIdx.x * blockDim.x + threadIdx.x) >> 5);
    int warp = threadIdx.x >> 5;
    int lane = threadIdx.x & 31;
    if (w >= EE) return;

    float dt = delta_t[w];
    int src = ei_src[w];

    float sn[8], cn[8];
    #pragma unroll
    for (int m = 0; m < 8; m++) {
        // freq = 1000^{-m/8}
        float freq = exp2f(-(float)m * (9.965784284662087f / 8.0f));
        sincosf(dt * freq, &sn[m], &cn[m]);
    }

    float pt[8];
    float lsum = 0.0f;
    #pragma unroll
    for (int jj = 0; jj < 8; jj++) {
        int j = lane + jj * 32;
        float s = bts[j];
        #pragma unroll
        for (int m = 0; m < 8; m++) {
            s += sn[m] * Wts[(2 * m) * DD + j] + cn[m] * Wts[(2 * m + 1) * DD + j];
        }
        pt[jj] = s;
        lsum += s;
    }
    #pragma unroll
    for (int o = 16; o; o >>= 1) lsum += __shfl_xor_sync(0xffffffffu, lsum, o);
    float mu = lsum * (1.0f / 256.0f);

    float lvar = 0.0f;
    #pragma unroll
    for (int jj = 0; jj < 8; jj++) { float d = pt[jj] - mu; lvar += d * d; }
    #pragma unroll
    for (int o = 16; o; o >>= 1) lvar += __shfl_xor_sync(0xffffffffu, lvar, o);
    float rstd = rsqrtf(lvar * (1.0f / 256.0f) + 1e-5f);

    // write strided-layout values to smem, re-read contiguously, vector-RED out
    #pragma unroll
    for (int jj = 0; jj < 8; jj++) {
        int j = lane + jj * 32;
        tr[warp][j] = (pt[jj] - mu) * rstd * gs[j] + bs[j];
    }
    __syncwarp();
    float4 y0 = *(const float4*)&tr[warp][lane * 8];
    float4 y1 = *(const float4*)&tr[warp][lane * 8 + 4];
    float* xp = &g_xw[(size_t)src * DD + lane * 8];
    red_add_v4(xp,     y0.x, y0.y, y0.z, y0.w);
    red_add_v4(xp + 4, y1.x, y1.y, y1.z, y1.w);
}

// ---------------- C = A(N,256) * W(256,256)^T + b, 128x128x8, double-buffered ----------------
// FUSE: gelu applied to A on load; epilogue does gated skip and writes final output.
template <bool FUSE>
__global__ void gemm128(const float* __restrict__ A, const float* __restrict__ W,
                        const float* __restrict__ bias, float* __restrict__ C, int N,
                        const float* __restrict__ xsrc, const float* __restrict__ skipv)
{
    __shared__ float As[2][8][128];
    __shared__ float Bs[2][8][128];

    int tid = threadIdx.x;
    int tx = tid & 15;    // column octet
    int ty = tid >> 4;    // row octet
    int rowBase = blockIdx.x * 128;
    int colBase = blockIdx.y * 128;

    float acc[8][8];
    #pragma unroll
    for (int i = 0; i < 8; i++)
        #pragma unroll
        for (int j = 0; j < 8; j++) acc[i][j] = 0.0f;

    int ldIdx = tid * 4;
    int lr = ldIdx >> 3;   // 0..127
    int lk = ldIdx & 7;    // 0 or 4
    int gr = rowBase + lr;
    int gc = colBase + lr;  // always < 256

    auto ldA = [&](int kt) -> float4 {
        float4 r = make_float4(0.f, 0.f, 0.f, 0.f);
        if (gr < N) r = *(const float4*)(A + (size_t)gr * 256 + kt + lk);
        if (FUSE) {
            r.x = gelu_exact(r.x); r.y = gelu_exact(r.y);
            r.z = gelu_exact(r.z); r.w = gelu_exact(r.w);
        }
        return r;
    };
    auto ldB = [&](int kt) -> float4 {
        return *(const float4*)(W + (size_t)gc * 256 + kt + lk);
    };
    auto stA = [&](int buf, float4 v) {
        As[buf][lk + 0][lr] = v.x; As[buf][lk + 1][lr] = v.y;
        As[buf][lk + 2][lr] = v.z; As[buf][lk + 3][lr] = v.w;
    };
    auto stB = [&](int buf, float4 v) {
        Bs[buf][lk + 0][lr] = v.x; Bs[buf][lk + 1][lr] = v.y;
        Bs[buf][lk + 2][lr] = v.z; Bs[buf][lk + 3][lr] = v.w;
    };

    stA(0, ldA(0));
    stB(0, ldB(0));
    __syncthreads();

    for (int t = 0; t < 32; t++) {
        int cur = t & 1;
        float4 an, bn;
        if (t < 31) { an = ldA((t + 1) * 8); bn = ldB((t + 1) * 8); }

        #pragma unroll
        for (int kk = 0; kk < 8; kk++) {
            float a[8], b[8];
            *(float4*)(a)     = *(const float4*)&As[cur][kk][ty * 8];
            *(float4*)(a + 4) = *(const float4*)&As[cur][kk][ty * 8 + 4];
            *(float4*)(b)     = *(const float4*)&Bs[cur][kk][tx * 8];
            *(float4*)(b + 4) = *(const float4*)&Bs[cur][kk][tx * 8 + 4];
            #pragma unroll
            for (int i = 0; i < 8; i++)
                #pragma unroll
                for (int j = 0; j < 8; j++) acc[i][j] += a[i] * b[j];
        }
        __syncthreads();
        if (t < 31) {
            stA(cur ^ 1, an);
            stB(cur ^ 1, bn);
            __syncthreads();
        }
    }

    float sa = 0.0f;
    if (FUSE) sa = 1.0f / (1.0f + expf(-skipv[0]));

    #pragma unroll
    for (int i = 0; i < 8; i++) {
        int r = rowBase + ty * 8 + i;
        if (r >= N) continue;
        #pragma unroll
        for (int j = 0; j < 8; j++) {
            int c = colBase + tx * 8 + j;
            float o = acc[i][j] + bias[c];
            if (FUSE) {
                C[(size_t)r * 256 + c] = sa * o + (1.0f - sa) * xsrc[(size_t)r * 256 + c];
            } else {
                C[(size_t)r * 256 + c] = o;
            }
        }
    }
}

// ---------------- per-node relation transform: KT = k @ a_rel[e], VT = v @ m_rel[e] ----------------
__global__ void rel_transform(const float* __restrict__ ktab, const float* __restrict__ vtab,
                              const float* __restrict__ arel, const float* __restrict__ mrel,
                              float* __restrict__ KT, float* __restrict__ VT, int N)
{
    int h = blockIdx.y;
    __shared__ float a_s[32 * 32], m_s[32 * 32];
    for (int i = threadIdx.x; i < 1024; i += 256) {
        a_s[i] = arel[h * 1024 + i];
        m_s[i] = mrel[h * 1024 + i];
    }
    __syncthreads();

    int warp = threadIdx.x >> 5, lane = threadIdx.x & 31;
    int n = blockIdx.x * 64 + warp * 8;
    #pragma unroll 1
    for (int t = 0; t < 8; t++, n++) {
        if (n >= N) break;
        float kv = ktab[(size_t)n * 256 + h * 32 + lane];
        float vv = vtab[(size_t)n * 256 + h * 32 + lane];
        float sk = 0.0f, sv = 0.0f;
        #pragma unroll
        for (int f = 0; f < 32; f++) {
            float kf = __shfl_sync(0xffffffffu, kv, f);
            float vf = __shfl_sync(0xffffffffu, vv, f);
            sk += kf * a_s[f * 32 + lane];
            sv += vf * m_s[f * 32 + lane];
        }
        KT[(size_t)n * 256 + h * 32 + lane] = sk;
        VT[(size_t)n * 256 + h * 32 + lane] = sv;
    }
}

// ---------------- fused attention edge pass: score + unnormalized scatter ----------------
// one warp per edge. out_num[dst] += exp(alpha)*V_e; denom[dst,h] += exp(alpha).
__global__ void attn_edge(const int* __restrict__ ei,
                          const float* __restrict__ qtab,
                          const float* __restrict__ prel,
                          float* __restrict__ denom)
{
    int w = (int)((blockIdx.x * blockDim.x + threadIdx.x) >> 5);
    int lane = threadIdx.x & 31;
    if (w >= EE) return;
    int src = ei[w];
    int dst = ei[EE + w];

    const float4* qp = (const float4*)(qtab + (size_t)dst * 256);
    const float4* kp = (const float4*)(g_KT + (size_t)src * 256);
    const float4* vp = (const float4*)(g_VT + (size_t)src * 256);
    float4 q0 = qp[lane * 2], q1 = qp[lane * 2 + 1];
    float4 k0 = kp[lane * 2], k1 = kp[lane * 2 + 1];
    float4 v0 = vp[lane * 2], v1 = vp[lane * 2 + 1];

    float s = q0.x * k0.x + q0.y * k0.y + q0.z * k0.z + q0.w * k0.w
            + q1.x * k1.x + q1.y * k1.y + q1.z * k1.z + q1.w * k1.w;
    s += __shfl_xor_sync(0xffffffffu, s, 1);
    s += __shfl_xor_sync(0xffffffffu, s, 2);
    int h = lane >> 2;
    float alpha = s * prel[h] * 0.17677669529663687f;  // 1/sqrt(32)
    float ev = expf(alpha);
    if ((lane & 3) == 0) atomicAdd(&denom[(size_t)dst * 8 + h], ev);

    float* np = g_num + (size_t)dst * 256 + lane * 8;
    red_add_v4(np,     v0.x * ev, v0.y * ev, v0.z * ev, v0.w * ev);
    red_add_v4(np + 4, v1.x * ev, v1.y * ev, v1.z * ev, v1.w * ev);
}

// ---------------- normalize numerator and fold into accumulator; re-zero num ----------------
__global__ void normalize_add(const float* __restrict__ denom,
                              float* __restrict__ acc, int Nd)
{
    int i = blockIdx.x * blockDim.x + threadIdx.x;
    if (i >= Nd * 64) return;            // 64 float4s per row
    int n = i >> 6;
    int c4 = i & 63;
    int h = c4 >> 3;                     // 8 float4s per head
    float4* np = (float4*)g_num;
    float4 v = np[i];
    np[i] = make_float4(0.f, 0.f, 0.f, 0.f);
    float d = denom[(size_t)n * 8 + h];
    float inv = d > 0.f ? 1.0f / d : 0.0f;
    float4* ap = (float4*)acc;
    float4 a = ap[i];
    a.x += v.x * inv; a.y += v.y * inv; a.z += v.z * inv; a.w += v.w * inv;
    ap[i] = a;
}

// ---------------- host side ----------------
static float* symaddr(const void* sym) {
    void* p = nullptr;
    cudaGetSymbolAddress(&p, sym);
    return (float*)p;
}

extern "C" void kernel_launch(void* const* d_in, const int* in_sizes, int n_in,
                              void* d_out, int out_size)
{
    const float* x_op    = (const float*)d_in[0];
    const float* x_m     = (const float*)d_in[1];
    const float* delta_t = (const float*)d_in[2];
    const int*   ei[4]   = {(const int*)d_in[3], (const int*)d_in[4],
                            (const int*)d_in[5], (const int*)d_in[6]};
    const float* Wt   = (const float*)d_in[7];
    const float* bt   = (const float*)d_in[8];
    const float* ln_g = (const float*)d_in[9];
    const float* ln_b = (const float*)d_in[10];
    const float* Wk   = (const float*)d_in[11];
    const float* bk   = (const float*)d_in[12];
    const float* Wq   = (const float*)d_in[13];
    const float* bq   = (const float*)d_in[14];
    const float* Wv   = (const float*)d_in[15];
    const float* bv   = (const float*)d_in[16];
    const float* Wa   = (const float*)d_in[17];
    const float* ba   = (const float*)d_in[18];
    const float* skip = (const float*)d_in[19];
    const float* a_rel = (const float*)d_in[20];
    const float* m_rel = (const float*)d_in[21];
    const float* p_rel = (const float*)d_in[22];
    float* out = (float*)d_out;

    float* xw    = symaddr(g_xw);
    float* k_op  = symaddr(g_k_op);
    float* q_op  = symaddr(g_q_op);
    float* v_op  = symaddr(g_v_op);
    float* k_m   = symaddr(g_k_m);
    float* q_m   = symaddr(g_q_m);
    float* v_m   = symaddr(g_v_m);
    float* KT    = symaddr(g_KT);
    float* VT    = symaddr(g_VT);
    float* denom = symaddr(g_denom);
    float* acc_op = symaddr(g_acc_op);
    float* acc_m  = symaddr(g_acc_m);

    cudaMemcpyAsync(xw, x_op, (size_t)NOP * DD * sizeof(float), cudaMemcpyDeviceToDevice);
    cudaMemsetAsync(acc_op, 0, (size_t)NOP * DD * sizeof(float));
    cudaMemsetAsync(acc_m, 0, (size_t)NMM * DD * sizeof(float));
    // g_num starts zero (static init) and is re-zeroed by normalize_add each pass.

    // temporal encoding: warp per edge on ei_mp, vector-RED into xw
    temporal_kernel<<<(EE + 7) / 8, 256>>>(delta_t, ei[0], Wt, bt, ln_g, ln_b);

    // k/q/v projections
    dim3 gOp((NOP + 127) / 128, 2);
    dim3 gM((NMM + 127) / 128, 2);
    gemm128<false><<<gOp, 256>>>(xw, Wk, bk, k_op, NOP, nullptr, nullptr);
    gemm128<false><<<gOp, 256>>>(xw, Wq, bq, q_op, NOP, nullptr, nullptr);
    gemm128<false><<<gOp, 256>>>(xw, Wv, bv, v_op, NOP, nullptr, nullptr);
    gemm128<false><<<gM, 256>>>(x_m, Wk + DD * DD, bk + DD, k_m, NMM, nullptr, nullptr);
    gemm128<false><<<gM, 256>>>(x_m, Wq + DD * DD, bq + DD, q_m, NMM, nullptr, nullptr);
    gemm128<false><<<gM, 256>>>(x_m, Wv + DD * DD, bv + DD, v_m, NMM, nullptr, nullptr);

    const int stype[4] = {0, 0, 0, 1};
    const int dtype[4] = {0, 0, 1, 0};
    for (int e = 0; e < 4; e++) {
        const float* ktab = stype[e] ? k_m : k_op;
        const float* vtab = stype[e] ? v_m : v_op;
        const float* qtab = dtype[e] ? q_m : q_op;
        int Ns = stype[e] ? NMM : NOP;
        int Nd = dtype[e] ? NMM : NOP;
        float* acc = dtype[e] ? acc_m : acc_op;

        dim3 gt((Ns + 63) / 64, 8);
        rel_transform<<<gt, 256>>>(ktab, vtab,
                                   a_rel + (size_t)e * HH * DHD * DHD,
                                   m_rel + (size_t)e * HH * DHD * DHD,
                                   KT, VT, Ns);
        cudaMemsetAsync(denom, 0, (size_t)Nd * HH * sizeof(float));
        attn_edge<<<(EE + 7) / 8, 256>>>(ei[e], qtab, p_rel + (size_t)e * HH, denom);
        normalize_add<<<(Nd * 64 + 255) / 256, 256>>>(denom, acc, Nd);
    }

    // final: res = sigmoid(skip) * (gelu(acc) @ Wa^T + ba) + (1 - sigmoid(skip)) * x
    gemm128<true><<<gOp, 256>>>(acc_op, Wa, ba, out, NOP, xw, skip);
    gemm128<true><<<gM, 256>>>(acc_m, Wa + DD * DD, ba + DD, out + (size_t)NOP * DD, NMM, x_m, skip + 1);
}

// round 6
// speedup vs baseline: 1.8489x; 1.2530x over previous
#include <cuda_runtime.h>
#include <math.h>

#define NOP 20000
#define NMM 500
#define DD  256
#define HH  8
#define DHD 32
#define TDE 16
#define EE  200000

#define TILES_OP 314   // 157 rowblocks x 2 colblocks
#define TILES_M  8     // 4 x 2
#define TILES_ALL (TILES_OP + TILES_M)

// ---------------- scratch (static device globals; no allocation) ----------------
__device__ float g_xw[NOP * DD];        // temporally-updated x_op
__device__ float g_k_op[NOP * DD];
__device__ float g_q_op[NOP * DD];
__device__ float g_v_op[NOP * DD];
__device__ float g_k_m[NMM * DD];
__device__ float g_q_m[NMM * DD];
__device__ float g_v_m[NMM * DD];
__device__ float g_KT[NOP * DD];        // per-edge-type transformed keys (reused)
__device__ float g_VT[NOP * DD];        // per-edge-type transformed values (reused)
__device__ float g_acc_op[NOP * DD];
__device__ float g_acc_m[NMM * DD];
__device__ int   g_off[NOP + 1];        // CSR offsets (by dst)
__device__ int   g_cur[NOP];            // degree counter / fill cursor
__device__ int   g_esrc[EE];            // src node per edge, grouped by dst

__device__ __forceinline__ float gelu_exact(float x) {
    return 0.5f * x * (1.0f + erff(x * 0.70710678118654752f));
}

// vector reduction-add to global memory (sm_90+). 16B-aligned address required.
__device__ __forceinline__ void red_add_v4(float* p, float a, float b, float c, float d) {
    asm volatile("red.global.add.v4.f32 [%0], {%1, %2, %3, %4};"
                 :: "l"(p), "f"(a), "f"(b), "f"(c), "f"(d) : "memory");
}

// ---------------- temporal encoding: one warp per edge ----------------
__global__ void temporal_kernel(const float* __restrict__ delta_t,
                                const int* __restrict__ ei_src,
                                const float* __restrict__ Wt,
                                const float* __restrict__ bt,
                                const float* __restrict__ ln_g,
                                const float* __restrict__ ln_b)
{
    __shared__ float Wts[TDE * DD];   // transposed: Wts[i*DD + j] = Wt[j*TDE + i]
    __shared__ float bts[DD], gs[DD], bs[DD];
    __shared__ float tr[8][DD];       // per-warp transpose staging
    for (int idx = threadIdx.x; idx < DD * TDE; idx += blockDim.x) {
        int j = idx / TDE, i = idx % TDE;
        Wts[i * DD + j] = Wt[idx];
    }
    for (int idx = threadIdx.x; idx < DD; idx += blockDim.x) {
        bts[idx] = bt[idx]; gs[idx] = ln_g[idx]; bs[idx] = ln_b[idx];
    }
    __syncthreads();

    int w = (int)((blockIdx.x * blockDim.x + threadIdx.x) >> 5);
    int warp = threadIdx.x >> 5;
    int lane = threadIdx.x & 31;
    if (w >= EE) return;

    float dt = delta_t[w];
    int src = ei_src[w];

    float sn[8], cn[8];
    #pragma unroll
    for (int m = 0; m < 8; m++) {
        float freq = exp2f(-(float)m * (9.965784284662087f / 8.0f));  // 1000^{-m/8}
        sincosf(dt * freq, &sn[m], &cn[m]);
    }

    float pt[8];
    float lsum = 0.0f;
    #pragma unroll
    for (int jj = 0; jj < 8; jj++) {
        int j = lane + jj * 32;
        float s = bts[j];
        #pragma unroll
        for (int m = 0; m < 8; m++) {
            s += sn[m] * Wts[(2 * m) * DD + j] + cn[m] * Wts[(2 * m + 1) * DD + j];
        }
        pt[jj] = s;
        lsum += s;
    }
    #pragma unroll
    for (int o = 16; o; o >>= 1) lsum += __shfl_xor_sync(0xffffffffu, lsum, o);
    float mu = lsum * (1.0f / 256.0f);

    float lvar = 0.0f;
    #pragma unroll
    for (int jj = 0; jj < 8; jj++) { float d = pt[jj] - mu; lvar += d * d; }
    #pragma unroll
    for (int o = 16; o; o >>= 1) lvar += __shfl_xor_sync(0xffffffffu, lvar, o);
    float rstd = rsqrtf(lvar * (1.0f / 256.0f) + 1e-5f);

    #pragma unroll
    for (int jj = 0; jj < 8; jj++) {
        int j = lane + jj * 32;
        tr[warp][j] = (pt[jj] - mu) * rstd * gs[j] + bs[j];
    }
    __syncwarp();
    float4 y0 = *(const float4*)&tr[warp][lane * 8];
    float4 y1 = *(const float4*)&tr[warp][lane * 8 + 4];
    float* xp = &g_xw[(size_t)src * DD + lane * 8];
    red_add_v4(xp,     y0.x, y0.y, y0.z, y0.w);
    red_add_v4(xp + 4, y1.x, y1.y, y1.z, y1.w);
}

// ---------------- GEMM core: 128x128x8 double-buffered tile body ----------------
// Computes one 128x128 tile of C = A(N,256) * W(256,256)^T + bias.
// FUSE: gelu(A) on load; epilogue gated skip: C = sa*o + (1-sa)*xsrc.
template <bool FUSE>
__device__ __forceinline__ void gemm_tile(const float* __restrict__ A,
                                          const float* __restrict__ W,
                                          const float* __restrict__ bias,
                                          float* __restrict__ C, int N,
                                          const float* __restrict__ xsrc,
                                          float sa,
                                          int rowBase, int colBase)
{
    __shared__ float As[2][8][128];
    __shared__ float Bs[2][8][128];

    int tid = threadIdx.x;
    int tx = tid & 15;
    int ty = tid >> 4;

    float acc[8][8];
    #pragma unroll
    for (int i = 0; i < 8; i++)
        #pragma unroll
        for (int j = 0; j < 8; j++) acc[i][j] = 0.0f;

    int ldIdx = tid * 4;
    int lr = ldIdx >> 3;   // 0..127
    int lk = ldIdx & 7;    // 0 or 4
    int gr = rowBase + lr;
    int gc = colBase + lr;

    auto ldA = [&](int kt) -> float4 {
        float4 r = make_float4(0.f, 0.f, 0.f, 0.f);
        if (gr < N) r = *(const float4*)(A + (size_t)gr * 256 + kt + lk);
        if (FUSE) {
            r.x = gelu_exact(r.x); r.y = gelu_exact(r.y);
            r.z = gelu_exact(r.z); r.w = gelu_exact(r.w);
        }
        return r;
    };
    auto ldB = [&](int kt) -> float4 {
        return *(const float4*)(W + (size_t)gc * 256 + kt + lk);
    };
    auto stA = [&](int buf, float4 v) {
        As[buf][lk + 0][lr] = v.x; As[buf][lk + 1][lr] = v.y;
        As[buf][lk + 2][lr] = v.z; As[buf][lk + 3][lr] = v.w;
    };
    auto stB = [&](int buf, float4 v) {
        Bs[buf][lk + 0][lr] = v.x; Bs[buf][lk + 1][lr] = v.y;
        Bs[buf][lk + 2][lr] = v.z; Bs[buf][lk + 3][lr] = v.w;
    };

    stA(0, ldA(0));
    stB(0, ldB(0));
    __syncthreads();

    for (int t = 0; t < 32; t++) {
        int cur = t & 1;
        float4 an, bn;
        if (t < 31) { an = ldA((t + 1) * 8); bn = ldB((t + 1) * 8); }

        #pragma unroll
        for (int kk = 0; kk < 8; kk++) {
            float a[8], b[8];
            *(float4*)(a)     = *(const float4*)&As[cur][kk][ty * 8];
            *(float4*)(a + 4) = *(const float4*)&As[cur][kk][ty * 8 + 4];
            *(float4*)(b)     = *(const float4*)&Bs[cur][kk][tx * 8];
            *(float4*)(b + 4) = *(const float4*)&Bs[cur][kk][tx * 8 + 4];
            #pragma unroll
            for (int i = 0; i < 8; i++)
                #pragma unroll
                for (int j = 0; j < 8; j++) acc[i][j] += a[i] * b[j];
        }
        __syncthreads();
        if (t < 31) {
            stA(cur ^ 1, an);
            stB(cur ^ 1, bn);
            __syncthreads();
        }
    }

    #pragma unroll
    for (int i = 0; i < 8; i++) {
        int r = rowBase + ty * 8 + i;
        if (r >= N) continue;
        #pragma unroll
        for (int j = 0; j < 8; j++) {
            int c = colBase + tx * 8 + j;
            float o = acc[i][j] + bias[c];
            if (FUSE) {
                C[(size_t)r * 256 + c] = sa * o + (1.0f - sa) * xsrc[(size_t)r * 256 + c];
            } else {
                C[(size_t)r * 256 + c] = o;
            }
        }
    }
}

// one launch: all 6 k/q/v GEMMs. grid (TILES_ALL, 1, 3); z: 0=k 1=q 2=v.
__global__ void __launch_bounds__(256) gemm_kqv(
    const float* __restrict__ Aop, const float* __restrict__ Am,
    const float* __restrict__ Wk, const float* __restrict__ Wq, const float* __restrict__ Wv,
    const float* __restrict__ bk, const float* __restrict__ bq, const float* __restrict__ bv,
    float* __restrict__ kop, float* __restrict__ qop, float* __restrict__ vop,
    float* __restrict__ km,  float* __restrict__ qm,  float* __restrict__ vm)
{
    int t = blockIdx.x;
    bool isM = t >= TILES_OP;
    int tt = isM ? t - TILES_OP : t;
    int rowBase = (tt >> 1) * 128;
    int colBase = (tt & 1) * 128;
    int z = blockIdx.z;

    const float* A = isM ? Am : Aop;
    int N = isM ? NMM : NOP;
    const float* W = (z == 0 ? Wk : z == 1 ? Wq : Wv) + (isM ? DD * DD : 0);
    const float* b = (z == 0 ? bk : z == 1 ? bq : bv) + (isM ? DD : 0);
    float* C = isM ? (z == 0 ? km : z == 1 ? qm : vm)
                   : (z == 0 ? kop : z == 1 ? qop : vop);

    gemm_tile<false>(A, W, b, C, N, nullptr, 0.0f, rowBase, colBase);
}

// one launch: both final FUSE GEMMs.
__global__ void __launch_bounds__(256) gemm_final(
    const float* __restrict__ accop, const float* __restrict__ accm,
    const float* __restrict__ Wa, const float* __restrict__ ba,
    const float* __restrict__ xop, const float* __restrict__ xm,
    const float* __restrict__ skipv, float* __restrict__ out)
{
    int t = blockIdx.x;
    bool isM = t >= TILES_OP;
    int tt = isM ? t - TILES_OP : t;
    int rowBase = (tt >> 1) * 128;
    int colBase = (tt & 1) * 128;

    const float* A = isM ? accm : accop;
    int N = isM ? NMM : NOP;
    const float* W = Wa + (isM ? DD * DD : 0);
    const float* b = ba + (isM ? DD : 0);
    const float* xs = isM ? xm : xop;
    float* C = out + (isM ? (size_t)NOP * DD : 0);
    float sa = 1.0f / (1.0f + expf(-skipv[isM ? 1 : 0]));

    gemm_tile<true>(A, W, b, C, N, xs, sa, rowBase, colBase);
}

// ---------------- per-node relation transform: KT = k @ a_rel[e], VT = v @ m_rel[e] ----------------
__global__ void rel_transform(const float* __restrict__ ktab, const float* __restrict__ vtab,
                              const float* __restrict__ arel, const float* __restrict__ mrel,
                              float* __restrict__ KT, float* __restrict__ VT, int N)
{
    int h = blockIdx.y;
    __shared__ float a_s[32 * 32], m_s[32 * 32];
    for (int i = threadIdx.x; i < 1024; i += 256) {
        a_s[i] = arel[h * 1024 + i];
        m_s[i] = mrel[h * 1024 + i];
    }
    __syncthreads();

    int warp = threadIdx.x >> 5, lane = threadIdx.x & 31;
    int n = blockIdx.x * 64 + warp * 8;
    #pragma unroll 1
    for (int t = 0; t < 8; t++, n++) {
        if (n >= N) break;
        float kv = ktab[(size_t)n * 256 + h * 32 + lane];
        float vv = vtab[(size_t)n * 256 + h * 32 + lane];
        float sk = 0.0f, sv = 0.0f;
        #pragma unroll
        for (int f = 0; f < 32; f++) {
            float kf = __shfl_sync(0xffffffffu, kv, f);
            float vf = __shfl_sync(0xffffffffu, vv, f);
            sk += kf * a_s[f * 32 + lane];
            sv += vf * m_s[f * 32 + lane];
        }
        KT[(size_t)n * 256 + h * 32 + lane] = sk;
        VT[(size_t)n * 256 + h * 32 + lane] = sv;
    }
}

// ---------------- CSR build (keyed by dst) ----------------
__global__ void csr_count(const int* __restrict__ ei) {
    int t = blockIdx.x * blockDim.x + threadIdx.x;
    if (t < EE) atomicAdd(&g_cur[ei[EE + t]], 1);
}

// single block, 1024 threads: exclusive scan of g_cur[0..Nd) -> g_off; g_cur := offset (fill cursor)
__global__ void csr_scan(int Nd) {
    __shared__ int sp[1024];
    int tid = threadIdx.x;
    int chunk = (Nd + 1023) / 1024;
    int beg = tid * chunk;
    int end = beg + chunk; if (end > Nd) end = Nd;
    int s = 0;
    for (int i = beg; i < end; i++) s += g_cur[i];
    sp[tid] = s;
    __syncthreads();
    #pragma unroll
    for (int o = 1; o < 1024; o <<= 1) {
        int v = (tid >= o) ? sp[tid - o] : 0;
        __syncthreads();
        sp[tid] += v;
        __syncthreads();
    }
    int base = (tid == 0) ? 0 : sp[tid - 1];
    for (int i = beg; i < end; i++) {
        int d = g_cur[i];
        g_off[i] = base;
        g_cur[i] = base;
        base += d;
    }
    if (tid == 1023) g_off[Nd] = sp[1023];
}

__global__ void csr_fill(const int* __restrict__ ei) {
    int t = blockIdx.x * blockDim.x + threadIdx.x;
    if (t >= EE) return;
    int dst = ei[EE + t];
    int src = ei[t];
    int pos = atomicAdd(&g_cur[dst], 1);
    g_esrc[pos] = src;
}

// ---------------- gather attention, op-dst: one warp per dst node, atomic-free ----------------
__global__ void attn_gather_op(const float* __restrict__ qtab,
                               const float* __restrict__ prel,
                               float* __restrict__ acc, int Nd)
{
    int w = (int)((blockIdx.x * blockDim.x + threadIdx.x) >> 5);
    int lane = threadIdx.x & 31;
    if (w >= Nd) return;
    int beg = g_off[w], end = g_off[w + 1];
    if (beg == end) return;

    const float4* qp = (const float4*)(qtab + (size_t)w * 256);
    float4 q0 = qp[lane * 2], q1 = qp[lane * 2 + 1];
    int h = lane >> 2;
    float ps = prel[h] * 0.17677669529663687f;   // 1/sqrt(32)

    float num[8] = {0.f, 0.f, 0.f, 0.f, 0.f, 0.f, 0.f, 0.f};
    float den = 0.0f;

    for (int j = beg; j < end; j++) {
        int src = g_esrc[j];
        const float4* kp = (const float4*)(g_KT + (size_t)src * 256);
        const float4* vp = (const float4*)(g_VT + (size_t)src * 256);
        float4 k0 = kp[lane * 2], k1 = kp[lane * 2 + 1];
        float4 v0 = vp[lane * 2], v1 = vp[lane * 2 + 1];
        float s = q0.x * k0.x + q0.y * k0.y + q0.z * k0.z + q0.w * k0.w
                + q1.x * k1.x + q1.y * k1.y + q1.z * k1.z + q1.w * k1.w;
        s += __shfl_xor_sync(0xffffffffu, s, 1);
        s += __shfl_xor_sync(0xffffffffu, s, 2);
        float ev = expf(s * ps);
        den += ev;
        num[0] += ev * v0.x; num[1] += ev * v0.y; num[2] += ev * v0.z; num[3] += ev * v0.w;
        num[4] += ev * v1.x; num[5] += ev * v1.y; num[6] += ev * v1.z; num[7] += ev * v1.w;
    }
    float rinv = 1.0f / den;
    float* ap = acc + (size_t)w * 256 + lane * 8;
    #pragma unroll
    for (int i = 0; i < 8; i++) ap[i] += num[i] * rinv;
}

// ---------------- gather attention, machine-dst (high degree): one block per dst node ----------------
__global__ void attn_gather_m(const float* __restrict__ qtab,
                              const float* __restrict__ prel,
                              float* __restrict__ acc, int Nd)
{
    int n = blockIdx.x;
    if (n >= Nd) return;
    __shared__ float snum[8][256];
    __shared__ float sden[8][8];
    int warp = threadIdx.x >> 5, lane = threadIdx.x & 31;
    int h = lane >> 2;
    int beg = g_off[n], end = g_off[n + 1];

    const float4* qp = (const float4*)(qtab + (size_t)n * 256);
    float4 q0 = qp[lane * 2], q1 = qp[lane * 2 + 1];
    float ps = prel[h] * 0.17677669529663687f;

    float num[8] = {0.f, 0.f, 0.f, 0.f, 0.f, 0.f, 0.f, 0.f};
    float den = 0.0f;

    for (int j = beg + warp; j < end; j += 8) {
        int src = g_esrc[j];
        const float4* kp = (const float4*)(g_KT + (size_t)src * 256);
        const float4* vp = (const float4*)(g_VT + (size_t)src * 256);
        float4 k0 = kp[lane * 2], k1 = kp[lane * 2 + 1];
        float4 v0 = vp[lane * 2], v1 = vp[lane * 2 + 1];
        float s = q0.x * k0.x + q0.y * k0.y + q0.z * k0.z + q0.w * k0.w
                + q1.x * k1.x + q1.y * k1.y + q1.z * k1.z + q1.w * k1.w;
        s += __shfl_xor_sync(0xffffffffu, s, 1);
        s += __shfl_xor_sync(0xffffffffu, s, 2);
        float ev = expf(s * ps);
        den += ev;
        num[0] += ev * v0.x; num[1] += ev * v0.y; num[2] += ev * v0.z; num[3] += ev * v0.w;
        num[4] += ev * v1.x; num[5] += ev * v1.y; num[6] += ev * v1.z; num[7] += ev * v1.w;
    }
    #pragma unroll
    for (int i = 0; i < 8; i += 4)
        *(float4*)&snum[warp][lane * 8 + i] = make_float4(num[i], num[i+1], num[i+2], num[i+3]);
    if ((lane & 3) == 0) sden[warp][h] = den;
    __syncthreads();

    if (end > beg) {
        int c = threadIdx.x;
        float tot = 0.0f;
        #pragma unroll
        for (int ww = 0; ww < 8; ww++) tot += snum[ww][c];
        int hh = c >> 5;
        float d = 0.0f;
        #pragma unroll
        for (int ww = 0; ww < 8; ww++) d += sden[ww][hh];
        acc[(size_t)n * 256 + c] += tot / d;
    }
}

// ---------------- host side ----------------
static float* symaddr(const void* sym) {
    void* p = nullptr;
    cudaGetSymbolAddress(&p, sym);
    return (float*)p;
}

extern "C" void kernel_launch(void* const* d_in, const int* in_sizes, int n_in,
                              void* d_out, int out_size)
{
    const float* x_op    = (const float*)d_in[0];
    const float* x_m     = (const float*)d_in[1];
    const float* delta_t = (const float*)d_in[2];
    const int*   ei[4]   = {(const int*)d_in[3], (const int*)d_in[4],
                            (const int*)d_in[5], (const int*)d_in[6]};
    const float* Wt   = (const float*)d_in[7];
    const float* bt   = (const float*)d_in[8];
    const float* ln_g = (const float*)d_in[9];
    const float* ln_b = (const float*)d_in[10];
    const float* Wk   = (const float*)d_in[11];
    const float* bk   = (const float*)d_in[12];
    const float* Wq   = (const float*)d_in[13];
    const float* bq   = (const float*)d_in[14];
    const float* Wv   = (const float*)d_in[15];
    const float* bv   = (const float*)d_in[16];
    const float* Wa   = (const float*)d_in[17];
    const float* ba   = (const float*)d_in[18];
    const float* skip = (const float*)d_in[19];
    const float* a_rel = (const float*)d_in[20];
    const float* m_rel = (const float*)d_in[21];
    const float* p_rel = (const float*)d_in[22];
    float* out = (float*)d_out;

    float* xw    = symaddr(g_xw);
    float* k_op  = symaddr(g_k_op);
    float* q_op  = symaddr(g_q_op);
    float* v_op  = symaddr(g_v_op);
    float* k_m   = symaddr(g_k_m);
    float* q_m   = symaddr(g_q_m);
    float* v_m   = symaddr(g_v_m);
    float* KT    = symaddr(g_KT);
    float* VT    = symaddr(g_VT);
    float* acc_op = symaddr(g_acc_op);
    float* acc_m  = symaddr(g_acc_m);
    int*   cur   = (int*)symaddr(g_cur);

    cudaMemcpyAsync(xw, x_op, (size_t)NOP * DD * sizeof(float), cudaMemcpyDeviceToDevice);
    cudaMemsetAsync(acc_op, 0, (size_t)NOP * DD * sizeof(float));
    cudaMemsetAsync(acc_m, 0, (size_t)NMM * DD * sizeof(float));

    // temporal encoding: warp per edge on ei_mp, vector-RED into xw
    temporal_kernel<<<(EE + 7) / 8, 256>>>(delta_t, ei[0], Wt, bt, ln_g, ln_b);

    // all 6 k/q/v projections in one launch
    {
        dim3 g(TILES_ALL, 1, 3);
        gemm_kqv<<<g, 256>>>(xw, x_m, Wk, Wq, Wv, bk, bq, bv,
                             k_op, q_op, v_op, k_m, q_m, v_m);
    }

    const int stype[4] = {0, 0, 0, 1};
    const int dtype[4] = {0, 0, 1, 0};
    for (int e = 0; e < 4; e++) {
        const float* ktab = stype[e] ? k_m : k_op;
        const float* vtab = stype[e] ? v_m : v_op;
        const float* qtab = dtype[e] ? q_m : q_op;
        int Ns = stype[e] ? NMM : NOP;
        int Nd = dtype[e] ? NMM : NOP;
        float* acc = dtype[e] ? acc_m : acc_op;

        // CSR build keyed by dst
        cudaMemsetAsync(cur, 0, (size_t)Nd * sizeof(int));
        csr_count<<<(EE + 255) / 256, 256>>>(ei[e]);
        csr_scan<<<1, 1024>>>(Nd);
        csr_fill<<<(EE + 255) / 256, 256>>>(ei[e]);

        dim3 gt((Ns + 63) / 64, 8);
        rel_transform<<<gt, 256>>>(ktab, vtab,
                                   a_rel + (size_t)e * HH * DHD * DHD,
                                   m_rel + (size_t)e * HH * DHD * DHD,
                                   KT, VT, Ns);

        if (dtype[e] == 0) {
            attn_gather_op<<<(Nd * 32 + 255) / 256, 256>>>(qtab, p_rel + (size_t)e * HH, acc, Nd);
        } else {
            attn_gather_m<<<Nd, 256>>>(qtab, p_rel + (size_t)e * HH, acc, Nd);
        }
    }

    // both final GEMMs in one launch
    gemm_final<<<TILES_ALL, 256>>>(acc_op, acc_m, Wa, ba, xw, x_m, skip, out);
}

// round 9
// speedup vs baseline: 2.0565x; 1.1123x over previous
#include <cuda_runtime.h>
#include <math.h>

#define NOP 20000
#define NMM 500
#define DD  256
#define HH  8
#define DHD 32
#define TDE 16
#define EE  200000

#define TILES_OP 314   // 157 rowblocks x 2 colblocks
#define TILES_M  8     // 4 x 2
#define TILES_ALL (TILES_OP + TILES_M)

// ---------------- scratch (static device globals; no allocation) ----------------
__device__ float g_xw[NOP * DD];        // temporally-updated x_op
__device__ float g_k_op[NOP * DD];
__device__ float g_q_op[NOP * DD];
__device__ float g_v_op[NOP * DD];
__device__ float g_k_m[NMM * DD];
__device__ float g_q_m[NMM * DD];
__device__ float g_v_m[NMM * DD];
__device__ float g_KT[3][NOP * DD];     // transformed keys for types 0,1,2 (op src)
__device__ float g_VT[3][NOP * DD];
__device__ float g_KTm[NMM * DD];       // type 3 (machine src)
__device__ float g_VTm[NMM * DD];
__device__ float g_acc_op[NOP * DD];
__device__ float g_acc_m[NMM * DD];
__device__ int   g_off4[4][NOP + 1];    // per-type CSR offsets (by dst)
__device__ int   g_cur4[4][NOP];        // per-type degree counter / fill cursor
__device__ int   g_esrc4[4][EE];        // per-type src list grouped by dst

__device__ __forceinline__ float gelu_exact(float x) {
    return 0.5f * x * (1.0f + erff(x * 0.70710678118654752f));
}

__device__ __forceinline__ void red_add_v4(float* p, float a, float b, float c, float d) {
    asm volatile("red.global.add.v4.f32 [%0], {%1, %2, %3, %4};"
                 :: "l"(p), "f"(a), "f"(b), "f"(c), "f"(d) : "memory");
}

// ---------------- temporal encoding: one warp per edge ----------------
__global__ void temporal_kernel(const float* __restrict__ delta_t,
                                const int* __restrict__ ei_src,
                                const float* __restrict__ Wt,
                                const float* __restrict__ bt,
                                const float* __restrict__ ln_g,
                                const float* __restrict__ ln_b)
{
    __shared__ float Wts[TDE * DD];   // transposed: Wts[i*DD + j] = Wt[j*TDE + i]
    __shared__ float bts[DD], gs[DD], bs[DD];
    __shared__ float tr[8][DD];       // per-warp transpose staging
    for (int idx = threadIdx.x; idx < DD * TDE; idx += blockDim.x) {
        int j = idx / TDE, i = idx % TDE;
        Wts[i * DD + j] = Wt[idx];
    }
    for (int idx = threadIdx.x; idx < DD; idx += blockDim.x) {
        bts[idx] = bt[idx]; gs[idx] = ln_g[idx]; bs[idx] = ln_b[idx];
    }
    __syncthreads();

    int w = (int)((blockIdx.x * blockDim.x + threadIdx.x) >> 5);
    int warp = threadIdx.x >> 5;
    int lane = threadIdx.x & 31;
    if (w >= EE) return;

    float dt = delta_t[w];
    int src = ei_src[w];

    float sn[8], cn[8];
    #pragma unroll
    for (int m = 0; m < 8; m++) {
        float freq = exp2f(-(float)m * (9.965784284662087f / 8.0f));  // 1000^{-m/8}
        sincosf(dt * freq, &sn[m], &cn[m]);
    }

    float pt[8];
    float lsum = 0.0f;
    #pragma unroll
    for (int jj = 0; jj < 8; jj++) {
        int j = lane + jj * 32;
        float s = bts[j];
        #pragma unroll
        for (int m = 0; m < 8; m++) {
            s += sn[m] * Wts[(2 * m) * DD + j] + cn[m] * Wts[(2 * m + 1) * DD + j];
        }
        pt[jj] = s;
        lsum += s;
    }
    #pragma unroll
    for (int o = 16; o; o >>= 1) lsum += __shfl_xor_sync(0xffffffffu, lsum, o);
    float mu = lsum * (1.0f / 256.0f);

    float lvar = 0.0f;
    #pragma unroll
    for (int jj = 0; jj < 8; jj++) { float d = pt[jj] - mu; lvar += d * d; }
    #pragma unroll
    for (int o = 16; o; o >>= 1) lvar += __shfl_xor_sync(0xffffffffu, lvar, o);
    float rstd = rsqrtf(lvar * (1.0f / 256.0f) + 1e-5f);

    #pragma unroll
    for (int jj = 0; jj < 8; jj++) {
        int j = lane + jj * 32;
        tr[warp][j] = (pt[jj] - mu) * rstd * gs[j] + bs[j];
    }
    __syncwarp();
    float4 y0 = *(const float4*)&tr[warp][lane * 8];
    float4 y1 = *(const float4*)&tr[warp][lane * 8 + 4];
    float* xp = &g_xw[(size_t)src * DD + lane * 8];
    red_add_v4(xp,     y0.x, y0.y, y0.z, y0.w);
    red_add_v4(xp + 4, y1.x, y1.y, y1.z, y1.w);
}

// ---------------- GEMM core: 128x128x8 double-buffered tile body ----------------
template <bool FUSE>
__device__ __forceinline__ void gemm_tile(const float* __restrict__ A,
                                          const float* __restrict__ W,
                                          const float* __restrict__ bias,
                                          float* __restrict__ C, int N,
                                          const float* __restrict__ xsrc,
                                          float sa,
                                          int rowBase, int colBase)
{
    __shared__ float As[2][8][128];
    __shared__ float Bs[2][8][128];

    int tid = threadIdx.x;
    int tx = tid & 15;
    int ty = tid >> 4;

    float acc[8][8];
    #pragma unroll
    for (int i = 0; i < 8; i++)
        #pragma unroll
        for (int j = 0; j < 8; j++) acc[i][j] = 0.0f;

    int ldIdx = tid * 4;
    int lr = ldIdx >> 3;   // 0..127
    int lk = ldIdx & 7;    // 0 or 4
    int gr = rowBase + lr;
    int gc = colBase + lr;

    auto ldA = [&](int kt) -> float4 {
        float4 r = make_float4(0.f, 0.f, 0.f, 0.f);
        if (gr < N) r = *(const float4*)(A + (size_t)gr * 256 + kt + lk);
        if (FUSE) {
            r.x = gelu_exact(r.x); r.y = gelu_exact(r.y);
            r.z = gelu_exact(r.z); r.w = gelu_exact(r.w);
        }
        return r;
    };
    auto ldB = [&](int kt) -> float4 {
        return *(const float4*)(W + (size_t)gc * 256 + kt + lk);
    };
    auto stA = [&](int buf, float4 v) {
        As[buf][lk + 0][lr] = v.x; As[buf][lk + 1][lr] = v.y;
        As[buf][lk + 2][lr] = v.z; As[buf][lk + 3][lr] = v.w;
    };
    auto stB = [&](int buf, float4 v) {
        Bs[buf][lk + 0][lr] = v.x; Bs[buf][lk + 1][lr] = v.y;
        Bs[buf][lk + 2][lr] = v.z; Bs[buf][lk + 3][lr] = v.w;
    };

    stA(0, ldA(0));
    stB(0, ldB(0));
    __syncthreads();

    for (int t = 0; t < 32; t++) {
        int cur = t & 1;
        float4 an, bn;
        if (t < 31) { an = ldA((t + 1) * 8); bn = ldB((t + 1) * 8); }

        #pragma unroll
        for (int kk = 0; kk < 8; kk++) {
            float a[8], b[8];
            *(float4*)(a)     = *(const float4*)&As[cur][kk][ty * 8];
            *(float4*)(a + 4) = *(const float4*)&As[cur][kk][ty * 8 + 4];
            *(float4*)(b)     = *(const float4*)&Bs[cur][kk][tx * 8];
            *(float4*)(b + 4) = *(const float4*)&Bs[cur][kk][tx * 8 + 4];
            #pragma unroll
            for (int i = 0; i < 8; i++)
                #pragma unroll
                for (int j = 0; j < 8; j++) acc[i][j] += a[i] * b[j];
        }
        __syncthreads();
        if (t < 31) {
            stA(cur ^ 1, an);
            stB(cur ^ 1, bn);
            __syncthreads();
        }
    }

    #pragma unroll
    for (int i = 0; i < 8; i++) {
        int r = rowBase + ty * 8 + i;
        if (r >= N) continue;
        #pragma unroll
        for (int j = 0; j < 8; j++) {
            int c = colBase + tx * 8 + j;
            float o = acc[i][j] + bias[c];
            if (FUSE) {
                C[(size_t)r * 256 + c] = sa * o + (1.0f - sa) * xsrc[(size_t)r * 256 + c];
            } else {
                C[(size_t)r * 256 + c] = o;
            }
        }
    }
}

// one launch: all 6 k/q/v GEMMs. grid (TILES_ALL, 1, 3); z: 0=k 1=q 2=v.
__global__ void __launch_bounds__(256) gemm_kqv(
    const float* __restrict__ Aop, const float* __restrict__ Am,
    const float* __restrict__ Wk, const float* __restrict__ Wq, const float* __restrict__ Wv,
    const float* __restrict__ bk, const float* __restrict__ bq, const float* __restrict__ bv,
    float* __restrict__ kop, float* __restrict__ qop, float* __restrict__ vop,
    float* __restrict__ km,  float* __restrict__ qm,  float* __restrict__ vm)
{
    int t = blockIdx.x;
    bool isM = t >= TILES_OP;
    int tt = isM ? t - TILES_OP : t;
    int rowBase = (tt >> 1) * 128;
    int colBase = (tt & 1) * 128;
    int z = blockIdx.z;

    const float* A = isM ? Am : Aop;
    int N = isM ? NMM : NOP;
    const float* W = (z == 0 ? Wk : z == 1 ? Wq : Wv) + (isM ? DD * DD : 0);
    const float* b = (z == 0 ? bk : z == 1 ? bq : bv) + (isM ? DD : 0);
    float* C = isM ? (z == 0 ? km : z == 1 ? qm : vm)
                   : (z == 0 ? kop : z == 1 ? qop : vop);

    gemm_tile<false>(A, W, b, C, N, nullptr, 0.0f, rowBase, colBase);
}

// one launch: both final FUSE GEMMs.
__global__ void __launch_bounds__(256) gemm_final(
    const float* __restrict__ accop, const float* __restrict__ accm,
    const float* __restrict__ Wa, const float* __restrict__ ba,
    const float* __restrict__ xop, const float* __restrict__ xm,
    const float* __restrict__ skipv, float* __restrict__ out)
{
    int t = blockIdx.x;
    bool isM = t >= TILES_OP;
    int tt = isM ? t - TILES_OP : t;
    int rowBase = (tt >> 1) * 128;
    int colBase = (tt & 1) * 128;

    const float* A = isM ? accm : accop;
    int N = isM ? NMM : NOP;
    const float* W = Wa + (isM ? DD * DD : 0);
    const float* b = ba + (isM ? DD : 0);
    const float* xs = isM ? xm : xop;
    float* C = out + (isM ? (size_t)NOP * DD : 0);
    float sa = 1.0f / (1.0f + expf(-skipv[isM ? 1 : 0]));

    gemm_tile<true>(A, W, b, C, N, xs, sa, rowBase, colBase);
}

// ---------------- rel transform, all 4 types in one launch ----------------
// grid: (ceil(NOP/64), 8 heads, 4 types). type 3 uses machine tables (NMM rows).
__global__ void rel_transform_all(const float* __restrict__ arel,
                                  const float* __restrict__ mrel)
{
    int e = blockIdx.z;
    int N = (e == 3) ? NMM : NOP;
    int warp = threadIdx.x >> 5, lane = threadIdx.x & 31;
    int nBase = blockIdx.x * 64;
    if (nBase >= N) return;

    const float* ktab = (e == 3) ? g_k_m : g_k_op;
    const float* vtab = (e == 3) ? g_v_m : g_v_op;
    float* KT = (e == 3) ? g_KTm : g_KT[e];
    float* VT = (e == 3) ? g_VTm : g_VT[e];

    int h = blockIdx.y;
    __shared__ float a_s[32 * 32], m_s[32 * 32];
    for (int i = threadIdx.x; i < 1024; i += 256) {
        a_s[i] = arel[((size_t)e * HH + h) * 1024 + i];
        m_s[i] = mrel[((size_t)e * HH + h) * 1024 + i];
    }
    __syncthreads();

    int n = nBase + warp * 8;
    #pragma unroll 1
    for (int t = 0; t < 8; t++, n++) {
        if (n >= N) break;
        float kv = ktab[(size_t)n * 256 + h * 32 + lane];
        float vv = vtab[(size_t)n * 256 + h * 32 + lane];
        float sk = 0.0f, sv = 0.0f;
        #pragma unroll
        for (int f = 0; f < 32; f++) {
            float kf = __shfl_sync(0xffffffffu, kv, f);
            float vf = __shfl_sync(0xffffffffu, vv, f);
            sk += kf * a_s[f * 32 + lane];
            sv += vf * m_s[f * 32 + lane];
        }
        KT[(size_t)n * 256 + h * 32 + lane] = sk;
        VT[(size_t)n * 256 + h * 32 + lane] = sv;
    }
}

// ---------------- batched CSR build (all 4 types) ----------------
__global__ void csr_count_all(const int* __restrict__ e0, const int* __restrict__ e1,
                              const int* __restrict__ e2, const int* __restrict__ e3) {
    int t = blockIdx.x * blockDim.x + threadIdx.x;
    if (t >= EE) return;
    int ty = blockIdx.y;
    const int* ei = (ty == 0) ? e0 : (ty == 1) ? e1 : (ty == 2) ? e2 : e3;
    atomicAdd(&g_cur4[ty][ei[EE + t]], 1);
}

// 4 blocks, one per type: exclusive scan of g_cur4[ty] -> g_off4[ty]; cur := offset
__global__ void csr_scan_all() {
    int ty = blockIdx.x;
    int Nd = (ty == 2) ? NMM : NOP;
    __shared__ int sp[1024];
    int tid = threadIdx.x;
    int chunk = (Nd + 1023) / 1024;
    int beg = tid * chunk;
    int end = beg + chunk; if (end > Nd) end = Nd;
    int s = 0;
    for (int i = beg; i < end; i++) s += g_cur4[ty][i];
    sp[tid] = s;
    __syncthreads();
    #pragma unroll
    for (int o = 1; o < 1024; o <<= 1) {
        int v = (tid >= o) ? sp[tid - o] : 0;
        __syncthreads();
        sp[tid] += v;
        __syncthreads();
    }
    int base = (tid == 0) ? 0 : sp[tid - 1];
    for (int i = beg; i < end; i++) {
        int d = g_cur4[ty][i];
        g_off4[ty][i] = base;
        g_cur4[ty][i] = base;
        base += d;
    }
    if (tid == 1023) g_off4[ty][Nd] = sp[1023];
}

__global__ void csr_fill_all(const int* __restrict__ e0, const int* __restrict__ e1,
                             const int* __restrict__ e2, const int* __restrict__ e3) {
    int t = blockIdx.x * blockDim.x + threadIdx.x;
    if (t >= EE) return;
    int ty = blockIdx.y;
    const int* ei = (ty == 0) ? e0 : (ty == 1) ? e1 : (ty == 2) ? e2 : e3;
    int dst = ei[EE + t];
    int src = ei[t];
    int pos = atomicAdd(&g_cur4[ty][dst], 1);
    g_esrc4[ty][pos] = src;
}

// ---------------- combined gather for op-dst types {0,1,3}: one warp per op node ----------------
__global__ void attn_gather_op(const float* __restrict__ prel)
{
    int w = (int)((blockIdx.x * blockDim.x + threadIdx.x) >> 5);
    int lane = threadIdx.x & 31;
    if (w >= NOP) return;

    const float4* qp = (const float4*)(g_q_op + (size_t)w * 256);
    float4 q0 = qp[lane * 2], q1 = qp[lane * 2 + 1];
    int h = lane >> 2;

    float out[8] = {0.f, 0.f, 0.f, 0.f, 0.f, 0.f, 0.f, 0.f};

    // types 0, 1 (op src), then 3 (machine src)
    #pragma unroll
    for (int pass = 0; pass < 3; pass++) {
        int e = (pass == 2) ? 3 : pass;
        const float* KT = (pass == 2) ? g_KTm : g_KT[e];
        const float* VT = (pass == 2) ? g_VTm : g_VT[e];
        float ps = prel[e * HH + h] * 0.17677669529663687f;   // 1/sqrt(32)

        int beg = g_off4[e][w], end = g_off4[e][w + 1];
        float num[8] = {0.f, 0.f, 0.f, 0.f, 0.f, 0.f, 0.f, 0.f};
        float den = 0.0f;
        #pragma unroll 2
        for (int j = beg; j < end; j++) {
            int src = g_esrc4[e][j];
            const float4* kp = (const float4*)(KT + (size_t)src * 256);
            const float4* vp = (const float4*)(VT + (size_t)src * 256);
            float4 k0 = kp[lane * 2], k1 = kp[lane * 2 + 1];
            float4 v0 = vp[lane * 2], v1 = vp[lane * 2 + 1];
            float s = q0.x * k0.x + q0.y * k0.y + q0.z * k0.z + q0.w * k0.w
                    + q1.x * k1.x + q1.y * k1.y + q1.z * k1.z + q1.w * k1.w;
            s += __shfl_xor_sync(0xffffffffu, s, 1);
            s += __shfl_xor_sync(0xffffffffu, s, 2);
            float ev = expf(s * ps);
            den += ev;
            num[0] += ev * v0.x; num[1] += ev * v0.y; num[2] += ev * v0.z; num[3] += ev * v0.w;
            num[4] += ev * v1.x; num[5] += ev * v1.y; num[6] += ev * v1.z; num[7] += ev * v1.w;
        }
        float inv = (den > 0.f) ? 1.0f / den : 0.0f;
        #pragma unroll
        for (int i = 0; i < 8; i++) out[i] += num[i] * inv;
    }

    float* ap = g_acc_op + (size_t)w * 256 + lane * 8;
    *(float4*)(ap)     = make_float4(out[0], out[1], out[2], out[3]);
    *(float4*)(ap + 4) = make_float4(out[4], out[5], out[6], out[7]);
}

// ---------------- gather for machine-dst type 2: one 512-thread block per machine node ----------------
__global__ void __launch_bounds__(512) attn_gather_m(const float* __restrict__ prel)
{
    int n = blockIdx.x;
    __shared__ float snum[16][256];
    __shared__ float sden[16][8];
    int warp = threadIdx.x >> 5, lane = threadIdx.x & 31;
    int h = lane >> 2;
    int beg = g_off4[2][n], end = g_off4[2][n + 1];

    const float4* qp = (const float4*)(g_q_m + (size_t)n * 256);
    float4 q0 = qp[lane * 2], q1 = qp[lane * 2 + 1];
    float ps = prel[2 * HH + h] * 0.17677669529663687f;

    float num[8] = {0.f, 0.f, 0.f, 0.f, 0.f, 0.f, 0.f, 0.f};
    float den = 0.0f;

    for (int j = beg + warp; j < end; j += 16) {
        int src = g_esrc4[2][j];
        const float4* kp = (const float4*)(g_KT[2] + (size_t)src * 256);
        const float4* vp = (const float4*)(g_VT[2] + (size_t)src * 256);
        float4 k0 = kp[lane * 2], k1 = kp[lane * 2 + 1];
        float4 v0 = vp[lane * 2], v1 = vp[lane * 2 + 1];
        float s = q0.x * k0.x + q0.y * k0.y + q0.z * k0.z + q0.w * k0.w
                + q1.x * k1.x + q1.y * k1.y + q1.z * k1.z + q1.w * k1.w;
        s += __shfl_xor_sync(0xffffffffu, s, 1);
        s += __shfl_xor_sync(0xffffffffu, s, 2);
        float ev = expf(s * ps);
        den += ev;
        num[0] += ev * v0.x; num[1] += ev * v0.y; num[2] += ev * v0.z; num[3] += ev * v0.w;
        num[4] += ev * v1.x; num[5] += ev * v1.y; num[6] += ev * v1.z; num[7] += ev * v1.w;
    }
    #pragma unroll
    for (int i = 0; i < 8; i += 4)
        *(float4*)&snum[warp][lane * 8 + i] = make_float4(num[i], num[i+1], num[i+2], num[i+3]);
    if ((lane & 3) == 0) sden[warp][h] = den;
    __syncthreads();

    if (threadIdx.x < 256) {
        int c = threadIdx.x;
        float tot = 0.0f;
        #pragma unroll
        for (int ww = 0; ww < 16; ww++) tot += snum[ww][c];
        int hh = c >> 5;
        float d = 0.0f;
        #pragma unroll
        for (int ww = 0; ww < 16; ww++) d += sden[ww][hh];
        g_acc_m[(size_t)n * 256 + c] = (d > 0.f) ? tot / d : 0.0f;
    }
}

// ---------------- host side ----------------
static float* symaddr(const void* sym) {
    void* p = nullptr;
    cudaGetSymbolAddress(&p, sym);
    return (float*)p;
}

extern "C" void kernel_launch(void* const* d_in, const int* in_sizes, int n_in,
                              void* d_out, int out_size)
{
    const float* x_op    = (const float*)d_in[0];
    const float* x_m     = (const float*)d_in[1];
    const float* delta_t = (const float*)d_in[2];
    const int*   ei0 = (const int*)d_in[3];
    const int*   ei1 = (const int*)d_in[4];
    const int*   ei2 = (const int*)d_in[5];
    const int*   ei3 = (const int*)d_in[6];
    const float* Wt   = (const float*)d_in[7];
    const float* bt   = (const float*)d_in[8];
    const float* ln_g = (const float*)d_in[9];
    const float* ln_b = (const float*)d_in[10];
    const float* Wk   = (const float*)d_in[11];
    const float* bk   = (const float*)d_in[12];
    const float* Wq   = (const float*)d_in[13];
    const float* bq   = (const float*)d_in[14];
    const float* Wv   = (const float*)d_in[15];
    const float* bv   = (const float*)d_in[16];
    const float* Wa   = (const float*)d_in[17];
    const float* ba   = (const float*)d_in[18];
    const float* skip = (const float*)d_in[19];
    const float* a_rel = (const float*)d_in[20];
    const float* m_rel = (const float*)d_in[21];
    const float* p_rel = (const float*)d_in[22];
    float* out = (float*)d_out;

    float* xw    = symaddr(g_xw);
    float* k_op  = symaddr(g_k_op);
    float* q_op  = symaddr(g_q_op);
    float* v_op  = symaddr(g_v_op);
    float* k_m   = symaddr(g_k_m);
    float* q_m   = symaddr(g_q_m);
    float* v_m   = symaddr(g_v_m);
    float* acc_op = symaddr(g_acc_op);
    float* acc_m  = symaddr(g_acc_m);
    int*   cur4  = (int*)symaddr(g_cur4);

    cudaMemcpyAsync(xw, x_op, (size_t)NOP * DD * sizeof(float), cudaMemcpyDeviceToDevice);
    cudaMemsetAsync(cur4, 0, (size_t)4 * NOP * sizeof(int));

    // temporal encoding: warp per edge on ei_mp, vector-RED into xw
    temporal_kernel<<<(EE + 7) / 8, 256>>>(delta_t, ei0, Wt, bt, ln_g, ln_b);

    // batched CSR build (all 4 types in 3 launches)
    {
        dim3 g((EE + 255) / 256, 4);
        csr_count_all<<<g, 256>>>(ei0, ei1, ei2, ei3);
        csr_scan_all<<<4, 1024>>>();
        csr_fill_all<<<g, 256>>>(ei0, ei1, ei2, ei3);
    }

    // all 6 k/q/v projections in one launch
    {
        dim3 g(TILES_ALL, 1, 3);
        gemm_kqv<<<g, 256>>>(xw, x_m, Wk, Wq, Wv, bk, bq, bv,
                             k_op, q_op, v_op, k_m, q_m, v_m);
    }

    // all 4 relation transforms in one launch
    {
        dim3 g((NOP + 63) / 64, HH, 4);
        rel_transform_all<<<g, 256>>>(a_rel, m_rel);
    }

    // gathers: op-dst types {0,1,3} combined; machine-dst type {2}
    attn_gather_op<<<(NOP * 32 + 255) / 256, 256>>>(p_rel);
    attn_gather_m<<<NMM, 512>>>(p_rel);

    // both final GEMMs in one launch
    gemm_final<<<TILES_ALL, 256>>>(acc_op, acc_m, Wa, ba, xw, x_m, skip, out);
}

// round 10
// speedup vs baseline: 2.1168x; 1.0293x over previous
#include <cuda_runtime.h>
#include <math.h>

#define NOP 20000
#define NMM 500
#define DD  256
#define HH  8
#define DHD 32
#define TDE 16
#define EE  200000

#define TILES_OP 314   // 157 rowblocks x 2 colblocks
#define TILES_M  8     // 4 x 2
#define TILES_ALL (TILES_OP + TILES_M)

#define TEMP_BLOCKS 25000          // (EE+7)/8 warps-per-edge temporal blocks
#define CNT_BPT 782                // count blocks per edge type: ceil(EE/256)
#define RELX 313                   // ceil(NOP/64)
#define REL_BLOCKS (RELX * HH * 4) // flattened rel_transform blocks
#define GOP_BLOCKS 2500            // NOP*32/256

// ---------------- scratch (static device globals; no allocation) ----------------
__device__ float g_xw[NOP * DD];
__device__ float g_k_op[NOP * DD];
__device__ float g_q_op[NOP * DD];
__device__ float g_v_op[NOP * DD];
__device__ float g_k_m[NMM * DD];
__device__ float g_q_m[NMM * DD];
__device__ float g_v_m[NMM * DD];
__device__ float g_KT[3][NOP * DD];
__device__ float g_VT[3][NOP * DD];
__device__ float g_KTm[NMM * DD];
__device__ float g_VTm[NMM * DD];
__device__ float g_acc_op[NOP * DD];
__device__ float g_acc_m[NMM * DD];
__device__ int   g_off4[4][NOP + 1];
__device__ int   g_cur4[4][NOP];
__device__ int   g_esrc4[4][EE];

__device__ __forceinline__ float gelu_exact(float x) {
    return 0.5f * x * (1.0f + erff(x * 0.70710678118654752f));
}

__device__ __forceinline__ void red_add_v4(float* p, float a, float b, float c, float d) {
    asm volatile("red.global.add.v4.f32 [%0], {%1, %2, %3, %4};"
                 :: "l"(p), "f"(a), "f"(b), "f"(c), "f"(d) : "memory");
}

// ---------------- temporal encoding body: one warp per edge ----------------
__device__ void temporal_body(int blk,
                              const float* __restrict__ delta_t,
                              const int* __restrict__ ei_src,
                              const float* __restrict__ Wt,
                              const float* __restrict__ bt,
                              const float* __restrict__ ln_g,
                              const float* __restrict__ ln_b)
{
    __shared__ float Wts[TDE * DD];
    __shared__ float bts[DD], gs[DD], bs[DD];
    __shared__ float tr[8][DD];
    for (int idx = threadIdx.x; idx < DD * TDE; idx += blockDim.x) {
        int j = idx / TDE, i = idx % TDE;
        Wts[i * DD + j] = Wt[idx];
    }
    for (int idx = threadIdx.x; idx < DD; idx += blockDim.x) {
        bts[idx] = bt[idx]; gs[idx] = ln_g[idx]; bs[idx] = ln_b[idx];
    }
    __syncthreads();

    int w = blk * 8 + (threadIdx.x >> 5);
    int warp = threadIdx.x >> 5;
    int lane = threadIdx.x & 31;
    if (w >= EE) return;

    float dt = delta_t[w];
    int src = ei_src[w];

    float sn[8], cn[8];
    #pragma unroll
    for (int m = 0; m < 8; m++) {
        float freq = exp2f(-(float)m * (9.965784284662087f / 8.0f));  // 1000^{-m/8}
        sincosf(dt * freq, &sn[m], &cn[m]);
    }

    float pt[8];
    float lsum = 0.0f;
    #pragma unroll
    for (int jj = 0; jj < 8; jj++) {
        int j = lane + jj * 32;
        float s = bts[j];
        #pragma unroll
        for (int m = 0; m < 8; m++) {
            s += sn[m] * Wts[(2 * m) * DD + j] + cn[m] * Wts[(2 * m + 1) * DD + j];
        }
        pt[jj] = s;
        lsum += s;
    }
    #pragma unroll
    for (int o = 16; o; o >>= 1) lsum += __shfl_xor_sync(0xffffffffu, lsum, o);
    float mu = lsum * (1.0f / 256.0f);

    float lvar = 0.0f;
    #pragma unroll
    for (int jj = 0; jj < 8; jj++) { float d = pt[jj] - mu; lvar += d * d; }
    #pragma unroll
    for (int o = 16; o; o >>= 1) lvar += __shfl_xor_sync(0xffffffffu, lvar, o);
    float rstd = rsqrtf(lvar * (1.0f / 256.0f) + 1e-5f);

    #pragma unroll
    for (int jj = 0; jj < 8; jj++) {
        int j = lane + jj * 32;
        tr[warp][j] = (pt[jj] - mu) * rstd * gs[j] + bs[j];
    }
    __syncwarp();
    float4 y0 = *(const float4*)&tr[warp][lane * 8];
    float4 y1 = *(const float4*)&tr[warp][lane * 8 + 4];
    float* xp = &g_xw[(size_t)src * DD + lane * 8];
    red_add_v4(xp,     y0.x, y0.y, y0.z, y0.w);
    red_add_v4(xp + 4, y1.x, y1.y, y1.z, y1.w);
}

// ---------------- launch 1: temporal + CSR count (independent) ----------------
__global__ void __launch_bounds__(256) fused_temporal_count(
    const float* __restrict__ delta_t,
    const int* __restrict__ e0, const int* __restrict__ e1,
    const int* __restrict__ e2, const int* __restrict__ e3,
    const float* __restrict__ Wt, const float* __restrict__ bt,
    const float* __restrict__ ln_g, const float* __restrict__ ln_b)
{
    int b = blockIdx.x;
    if (b < TEMP_BLOCKS) {
        temporal_body(b, delta_t, e0, Wt, bt, ln_g, ln_b);
    } else {
        int cb = b - TEMP_BLOCKS;
        int ty = cb / CNT_BPT;
        int i = (cb % CNT_BPT) * 256 + threadIdx.x;
        if (i < EE) {
            const int* ei = (ty == 0) ? e0 : (ty == 1) ? e1 : (ty == 2) ? e2 : e3;
            atomicAdd(&g_cur4[ty][ei[EE + i]], 1);
        }
    }
}

// ---------------- GEMM core: 128x128x16 double-buffered, ONE sync per k-tile ----------------
template <bool FUSE>
__device__ __forceinline__ void gemm_tile(const float* __restrict__ A,
                                          const float* __restrict__ W,
                                          const float* __restrict__ bias,
                                          float* __restrict__ C, int N,
                                          const float* __restrict__ xsrc,
                                          float sa,
                                          int rowBase, int colBase)
{
    __shared__ float As[2][16][132];
    __shared__ float Bs[2][16][132];

    int tid = threadIdx.x;
    int tx = tid & 15;
    int ty = tid >> 4;

    float acc[8][8];
    #pragma unroll
    for (int i = 0; i < 8; i++)
        #pragma unroll
        for (int j = 0; j < 8; j++) acc[i][j] = 0.0f;

    // loader: 512 float4s per tile (128 rows x 16 k), 2 per thread
    int row0 = tid >> 2,            kq0 = (tid & 3) * 4;
    int row1 = (tid + 256) >> 2,    kq1 = ((tid + 256) & 3) * 4;
    int gr0 = rowBase + row0, gr1 = rowBase + row1;
    int gc0 = colBase + row0, gc1 = colBase + row1;

    float4 av0, av1, bv0, bv1;
    auto ldg = [&](int kt) {
        av0 = make_float4(0.f, 0.f, 0.f, 0.f);
        av1 = make_float4(0.f, 0.f, 0.f, 0.f);
        if (gr0 < N) av0 = *(const float4*)(A + (size_t)gr0 * 256 + kt + kq0);
        if (gr1 < N) av1 = *(const float4*)(A + (size_t)gr1 * 256 + kt + kq1);
        if (FUSE) {
            av0.x = gelu_exact(av0.x); av0.y = gelu_exact(av0.y);
            av0.z = gelu_exact(av0.z); av0.w = gelu_exact(av0.w);
            av1.x = gelu_exact(av1.x); av1.y = gelu_exact(av1.y);
            av1.z = gelu_exact(av1.z); av1.w = gelu_exact(av1.w);
        }
        bv0 = *(const float4*)(W + (size_t)gc0 * 256 + kt + kq0);
        bv1 = *(const float4*)(W + (size_t)gc1 * 256 + kt + kq1);
    };
    auto sts = [&](int buf) {
        As[buf][kq0 + 0][row0] = av0.x; As[buf][kq0 + 1][row0] = av0.y;
        As[buf][kq0 + 2][row0] = av0.z; As[buf][kq0 + 3][row0] = av0.w;
        As[buf][kq1 + 0][row1] = av1.x; As[buf][kq1 + 1][row1] = av1.y;
        As[buf][kq1 + 2][row1] = av1.z; As[buf][kq1 + 3][row1] = av1.w;
        Bs[buf][kq0 + 0][row0] = bv0.x; Bs[buf][kq0 + 1][row0] = bv0.y;
        Bs[buf][kq0 + 2][row0] = bv0.z; Bs[buf][kq0 + 3][row0] = bv0.w;
        Bs[buf][kq1 + 0][row1] = bv1.x; Bs[buf][kq1 + 1][row1] = bv1.y;
        Bs[buf][kq1 + 2][row1] = bv1.z; Bs[buf][kq1 + 3][row1] = bv1.w;
    };

    ldg(0);
    sts(0);
    __syncthreads();

    for (int t = 0; t < 16; t++) {
        int cur = t & 1;
        if (t < 15) ldg((t + 1) * 16);

        #pragma unroll
        for (int kk = 0; kk < 16; kk++) {
            float a[8], b[8];
            *(float4*)(a)     = *(const float4*)&As[cur][kk][ty * 8];
            *(float4*)(a + 4) = *(const float4*)&As[cur][kk][ty * 8 + 4];
            *(float4*)(b)     = *(const float4*)&Bs[cur][kk][tx * 8];
            *(float4*)(b + 4) = *(const float4*)&Bs[cur][kk][tx * 8 + 4];
            #pragma unroll
            for (int i = 0; i < 8; i++)
                #pragma unroll
                for (int j = 0; j < 8; j++) acc[i][j] += a[i] * b[j];
        }
        if (t < 15) sts(cur ^ 1);
        __syncthreads();
    }

    #pragma unroll
    for (int i = 0; i < 8; i++) {
        int r = rowBase + ty * 8 + i;
        if (r >= N) continue;
        #pragma unroll
        for (int j = 0; j < 8; j++) {
            int c = colBase + tx * 8 + j;
            float o = acc[i][j] + bias[c];
            if (FUSE) {
                C[(size_t)r * 256 + c] = sa * o + (1.0f - sa) * xsrc[(size_t)r * 256 + c];
            } else {
                C[(size_t)r * 256 + c] = o;
            }
        }
    }
}

// 256-thread exclusive scan of g_cur4[ty] -> g_off4[ty]; cur := offset (fill cursor)
__device__ void csr_scan_body(int ty) {
    int Nd = (ty == 2) ? NMM : NOP;
    __shared__ int sp[256];
    int tid = threadIdx.x;
    int chunk = (Nd + 255) / 256;
    int beg = tid * chunk;
    int end = beg + chunk; if (end > Nd) end = Nd;
    int s = 0;
    for (int i = beg; i < end; i++) s += g_cur4[ty][i];
    sp[tid] = s;
    __syncthreads();
    #pragma unroll
    for (int o = 1; o < 256; o <<= 1) {
        int v = (tid >= o) ? sp[tid - o] : 0;
        __syncthreads();
        sp[tid] += v;
        __syncthreads();
    }
    int base = (tid == 0) ? 0 : sp[tid - 1];
    for (int i = beg; i < end; i++) {
        int d = g_cur4[ty][i];
        g_off4[ty][i] = base;
        g_cur4[ty][i] = base;
        base += d;
    }
    if (tid == 255) g_off4[ty][Nd] = sp[255];
}

// ---------------- launch 2: all 6 k/q/v GEMMs + 4 CSR scans ----------------
__global__ void __launch_bounds__(256) fused_kqv_scan(
    const float* __restrict__ Aop, const float* __restrict__ Am,
    const float* __restrict__ Wk, const float* __restrict__ Wq, const float* __restrict__ Wv,
    const float* __restrict__ bk, const float* __restrict__ bq, const float* __restrict__ bv,
    float* __restrict__ kop, float* __restrict__ qop, float* __restrict__ vop,
    float* __restrict__ km,  float* __restrict__ qm,  float* __restrict__ vm)
{
    int b = blockIdx.x;
    if (b < 3 * TILES_ALL) {
        int z = b / TILES_ALL;
        int t = b % TILES_ALL;
        bool isM = t >= TILES_OP;
        int tt = isM ? t - TILES_OP : t;
        int rowBase = (tt >> 1) * 128;
        int colBase = (tt & 1) * 128;

        const float* A = isM ? Am : Aop;
        int N = isM ? NMM : NOP;
        const float* W = (z == 0 ? Wk : z == 1 ? Wq : Wv) + (isM ? DD * DD : 0);
        const float* bb = (z == 0 ? bk : z == 1 ? bq : bv) + (isM ? DD : 0);
        float* C = isM ? (z == 0 ? km : z == 1 ? qm : vm)
                       : (z == 0 ? kop : z == 1 ? qop : vop);
        gemm_tile<false>(A, W, bb, C, N, nullptr, 0.0f, rowBase, colBase);
    } else {
        csr_scan_body(b - 3 * TILES_ALL);
    }
}

// ---------------- rel transform body (flattened) ----------------
__device__ void rel_body(int e, int h, int xb,
                         const float* __restrict__ arel,
                         const float* __restrict__ mrel)
{
    int N = (e == 3) ? NMM : NOP;
    int nBase = xb * 64;
    if (nBase >= N) return;

    const float* ktab = (e == 3) ? g_k_m : g_k_op;
    const float* vtab = (e == 3) ? g_v_m : g_v_op;
    float* KT = (e == 3) ? g_KTm : g_KT[e];
    float* VT = (e == 3) ? g_VTm : g_VT[e];

    __shared__ float a_s[32 * 32], m_s[32 * 32];
    for (int i = threadIdx.x; i < 1024; i += 256) {
        a_s[i] = arel[((size_t)e * HH + h) * 1024 + i];
        m_s[i] = mrel[((size_t)e * HH + h) * 1024 + i];
    }
    __syncthreads();

    int warp = threadIdx.x >> 5, lane = threadIdx.x & 31;
    int n = nBase + warp * 8;
    #pragma unroll 1
    for (int t = 0; t < 8; t++, n++) {
        if (n >= N) break;
        float kv = ktab[(size_t)n * 256 + h * 32 + lane];
        float vv = vtab[(size_t)n * 256 + h * 32 + lane];
        float sk = 0.0f, sv = 0.0f;
        #pragma unroll
        for (int f = 0; f < 32; f++) {
            float kf = __shfl_sync(0xffffffffu, kv, f);
            float vf = __shfl_sync(0xffffffffu, vv, f);
            sk += kf * a_s[f * 32 + lane];
            sv += vf * m_s[f * 32 + lane];
        }
        KT[(size_t)n * 256 + h * 32 + lane] = sk;
        VT[(size_t)n * 256 + h * 32 + lane] = sv;
    }
}

// ---------------- launch 3: rel transforms + CSR fill ----------------
__global__ void __launch_bounds__(256) fused_rel_fill(
    const float* __restrict__ arel, const float* __restrict__ mrel,
    const int* __restrict__ e0, const int* __restrict__ e1,
    const int* __restrict__ e2, const int* __restrict__ e3)
{
    int b = blockIdx.x;
    if (b < REL_BLOCKS) {
        int e = b / (RELX * HH);
        int rem = b % (RELX * HH);
        int h = rem / RELX;
        int xb = rem % RELX;
        rel_body(e, h, xb, arel, mrel);
    } else {
        int cb = b - REL_BLOCKS;
        int ty = cb / CNT_BPT;
        int i = (cb % CNT_BPT) * 256 + threadIdx.x;
        if (i < EE) {
            const int* ei = (ty == 0) ? e0 : (ty == 1) ? e1 : (ty == 2) ? e2 : e3;
            int dst = ei[EE + i];
            int src = ei[i];
            int pos = atomicAdd(&g_cur4[ty][dst], 1);
            g_esrc4[ty][pos] = src;
        }
    }
}

// ---------------- gather bodies ----------------
__device__ void gather_op_body(int b, const float* __restrict__ prel)
{
    int w = b * 8 + (threadIdx.x >> 5);
    int lane = threadIdx.x & 31;
    if (w >= NOP) return;

    const float4* qp = (const float4*)(g_q_op + (size_t)w * 256);
    float4 q0 = qp[lane * 2], q1 = qp[lane * 2 + 1];
    int h = lane >> 2;

    float out[8] = {0.f, 0.f, 0.f, 0.f, 0.f, 0.f, 0.f, 0.f};

    #pragma unroll
    for (int pass = 0; pass < 3; pass++) {
        int e = (pass == 2) ? 3 : pass;
        const float* KT = (pass == 2) ? g_KTm : g_KT[e];
        const float* VT = (pass == 2) ? g_VTm : g_VT[e];
        float ps = prel[e * HH + h] * 0.17677669529663687f;   // 1/sqrt(32)

        int beg = g_off4[e][w], end = g_off4[e][w + 1];
        float num[8] = {0.f, 0.f, 0.f, 0.f, 0.f, 0.f, 0.f, 0.f};
        float den = 0.0f;
        #pragma unroll 2
        for (int j = beg; j < end; j++) {
            int src = g_esrc4[e][j];
            const float4* kp = (const float4*)(KT + (size_t)src * 256);
            const float4* vp = (const float4*)(VT + (size_t)src * 256);
            float4 k0 = kp[lane * 2], k1 = kp[lane * 2 + 1];
            float4 v0 = vp[lane * 2], v1 = vp[lane * 2 + 1];
            float s = q0.x * k0.x + q0.y * k0.y + q0.z * k0.z + q0.w * k0.w
                    + q1.x * k1.x + q1.y * k1.y + q1.z * k1.z + q1.w * k1.w;
            s += __shfl_xor_sync(0xffffffffu, s, 1);
            s += __shfl_xor_sync(0xffffffffu, s, 2);
            float ev = expf(s * ps);
            den += ev;
            num[0] += ev * v0.x; num[1] += ev * v0.y; num[2] += ev * v0.z; num[3] += ev * v0.w;
            num[4] += ev * v1.x; num[5] += ev * v1.y; num[6] += ev * v1.z; num[7] += ev * v1.w;
        }
        float inv = (den > 0.f) ? 1.0f / den : 0.0f;
        #pragma unroll
        for (int i = 0; i < 8; i++) out[i] += num[i] * inv;
    }

    float* ap = g_acc_op + (size_t)w * 256 + lane * 8;
    *(float4*)(ap)     = make_float4(out[0], out[1], out[2], out[3]);
    *(float4*)(ap + 4) = make_float4(out[4], out[5], out[6], out[7]);
}

__device__ void gather_m_body(int n, const float* __restrict__ prel)
{
    __shared__ float snum[8][256];
    __shared__ float sden[8][8];
    int warp = threadIdx.x >> 5, lane = threadIdx.x & 31;
    int h = lane >> 2;
    int beg = g_off4[2][n], end = g_off4[2][n + 1];

    const float4* qp = (const float4*)(g_q_m + (size_t)n * 256);
    float4 q0 = qp[lane * 2], q1 = qp[lane * 2 + 1];
    float ps = prel[2 * HH + h] * 0.17677669529663687f;

    float num[8] = {0.f, 0.f, 0.f, 0.f, 0.f, 0.f, 0.f, 0.f};
    float den = 0.0f;

    for (int j = beg + warp; j < end; j += 8) {
        int src = g_esrc4[2][j];
        const float4* kp = (const float4*)(g_KT[2] + (size_t)src * 256);
        const float4* vp = (const float4*)(g_VT[2] + (size_t)src * 256);
        float4 k0 = kp[lane * 2], k1 = kp[lane * 2 + 1];
        float4 v0 = vp[lane * 2], v1 = vp[lane * 2 + 1];
        float s = q0.x * k0.x + q0.y * k0.y + q0.z * k0.z + q0.w * k0.w
                + q1.x * k1.x + q1.y * k1.y + q1.z * k1.z + q1.w * k1.w;
        s += __shfl_xor_sync(0xffffffffu, s, 1);
        s += __shfl_xor_sync(0xffffffffu, s, 2);
        float ev = expf(s * ps);
        den += ev;
        num[0] += ev * v0.x; num[1] += ev * v0.y; num[2] += ev * v0.z; num[3] += ev * v0.w;
        num[4] += ev * v1.x; num[5] += ev * v1.y; num[6] += ev * v1.z; num[7] += ev * v1.w;
    }
    #pragma unroll
    for (int i = 0; i < 8; i += 4)
        *(float4*)&snum[warp][lane * 8 + i] = make_float4(num[i], num[i+1], num[i+2], num[i+3]);
    if ((lane & 3) == 0) sden[warp][h] = den;
    __syncthreads();

    {
        int c = threadIdx.x;
        float tot = 0.0f;
        #pragma unroll
        for (int ww = 0; ww < 8; ww++) tot += snum[ww][c];
        int hh = c >> 5;
        float d = 0.0f;
        #pragma unroll
        for (int ww = 0; ww < 8; ww++) d += sden[ww][hh];
        g_acc_m[(size_t)n * 256 + c] = (d > 0.f) ? tot / d : 0.0f;
    }
}

// ---------------- launch 4: both gathers ----------------
__global__ void __launch_bounds__(256) fused_gather(const float* __restrict__ prel)
{
    int b = blockIdx.x;
    if (b < GOP_BLOCKS) gather_op_body(b, prel);
    else                gather_m_body(b - GOP_BLOCKS, prel);
}

// ---------------- launch 5: both final FUSE GEMMs ----------------
__global__ void __launch_bounds__(256) gemm_final(
    const float* __restrict__ accop, const float* __restrict__ accm,
    const float* __restrict__ Wa, const float* __restrict__ ba,
    const float* __restrict__ xop, const float* __restrict__ xm,
    const float* __restrict__ skipv, float* __restrict__ out)
{
    int t = blockIdx.x;
    bool isM = t >= TILES_OP;
    int tt = isM ? t - TILES_OP : t;
    int rowBase = (tt >> 1) * 128;
    int colBase = (tt & 1) * 128;

    const float* A = isM ? accm : accop;
    int N = isM ? NMM : NOP;
    const float* W = Wa + (isM ? DD * DD : 0);
    const float* b = ba + (isM ? DD : 0);
    const float* xs = isM ? xm : xop;
    float* C = out + (isM ? (size_t)NOP * DD : 0);
    float sa = 1.0f / (1.0f + expf(-skipv[isM ? 1 : 0]));

    gemm_tile<true>(A, W, b, C, N, xs, sa, rowBase, colBase);
}

// ---------------- host side ----------------
static float* symaddr(const void* sym) {
    void* p = nullptr;
    cudaGetSymbolAddress(&p, sym);
    return (float*)p;
}

extern "C" void kernel_launch(void* const* d_in, const int* in_sizes, int n_in,
                              void* d_out, int out_size)
{
    const float* x_op    = (const float*)d_in[0];
    const float* x_m     = (const float*)d_in[1];
    const float* delta_t = (const float*)d_in[2];
    const int*   ei0 = (const int*)d_in[3];
    const int*   ei1 = (const int*)d_in[4];
    const int*   ei2 = (const int*)d_in[5];
    const int*   ei3 = (const int*)d_in[6];
    const float* Wt   = (const float*)d_in[7];
    const float* bt   = (const float*)d_in[8];
    const float* ln_g = (const float*)d_in[9];
    const float* ln_b = (const float*)d_in[10];
    const float* Wk   = (const float*)d_in[11];
    const float* bk   = (const float*)d_in[12];
    const float* Wq   = (const float*)d_in[13];
    const float* bq   = (const float*)d_in[14];
    const float* Wv   = (const float*)d_in[15];
    const float* bv   = (const float*)d_in[16];
    const float* Wa   = (const float*)d_in[17];
    const float* ba   = (const float*)d_in[18];
    const float* skip = (const float*)d_in[19];
    const float* a_rel = (const float*)d_in[20];
    const float* m_rel = (const float*)d_in[21];
    const float* p_rel = (const float*)d_in[22];
    float* out = (float*)d_out;

    float* xw    = symaddr(g_xw);
    float* k_op  = symaddr(g_k_op);
    float* q_op  = symaddr(g_q_op);
    float* v_op  = symaddr(g_v_op);
    float* k_m   = symaddr(g_k_m);
    float* q_m   = symaddr(g_q_m);
    float* v_m   = symaddr(g_v_m);
    float* acc_op = symaddr(g_acc_op);
    float* acc_m  = symaddr(g_acc_m);
    int*   cur4  = (int*)symaddr(g_cur4);

    cudaMemcpyAsync(xw, x_op, (size_t)NOP * DD * sizeof(float), cudaMemcpyDeviceToDevice);
    cudaMemsetAsync(cur4, 0, (size_t)4 * NOP * sizeof(int));

    // L1: temporal encoding + CSR degree count
    fused_temporal_count<<<TEMP_BLOCKS + 4 * CNT_BPT, 256>>>(
        delta_t, ei0, ei1, ei2, ei3, Wt, bt, ln_g, ln_b);

    // L2: 6 k/q/v GEMMs + 4 CSR scans (scans hide under GEMM blocks)
    fused_kqv_scan<<<3 * TILES_ALL + 4, 256>>>(
        xw, x_m, Wk, Wq, Wv, bk, bq, bv,
        k_op, q_op, v_op, k_m, q_m, v_m);

    // L3: relation transforms + CSR fill
    fused_rel_fill<<<REL_BLOCKS + 4 * CNT_BPT, 256>>>(a_rel, m_rel, ei0, ei1, ei2, ei3);

    // L4: both gathers
    fused_gather<<<GOP_BLOCKS + NMM, 256>>>(p_rel);

    // L5: both final GEMMs
    gemm_final<<<TILES_ALL, 256>>>(acc_op, acc_m, Wa, ba, xw, x_m, skip, out);
}

// round 11
// speedup vs baseline: 2.7285x; 1.2889x over previous
#include <cuda_runtime.h>
#include <math.h>
#include <stdint.h>

#define NOP 20000
#define NMM 500
#define DD  256
#define HH  8
#define DHD 32
#define TDE 16
#define EE  200000

#define TILES_OP 314   // 157 rowblocks x 2 colblocks
#define TILES_M  8     // 4 x 2
#define TILES_ALL (TILES_OP + TILES_M)

#define TEMP_BLOCKS 782            // ceil(EE/256), 256 edges per block
#define CNT_BPT 782                // count blocks per edge type: ceil(EE/256)
#define RELX 313                   // ceil(NOP/64)
#define REL_BLOCKS (RELX * HH * 4)
#define GOP_BLOCKS 2500            // NOP*32/256

// ---------------- scratch ----------------
__device__ float g_xw[NOP * DD];
__device__ float g_k_op[NOP * DD];
__device__ float g_q_op[NOP * DD];
__device__ float g_v_op[NOP * DD];
__device__ float g_k_m[NMM * DD];
__device__ float g_q_m[NMM * DD];
__device__ float g_v_m[NMM * DD];
__device__ float g_KT[3][NOP * DD];
__device__ float g_VT[3][NOP * DD];
__device__ float g_KTm[NMM * DD];
__device__ float g_VTm[NMM * DD];
__device__ float g_acc_op[NOP * DD];
__device__ float g_acc_m[NMM * DD];
__device__ int   g_off4[4][NOP + 1];
__device__ int   g_cur4[4][NOP];
__device__ int   g_esrc4[4][EE];

__device__ __forceinline__ float gelu_exact(float x) {
    return 0.5f * x * (1.0f + erff(x * 0.70710678118654752f));
}

__device__ __forceinline__ void red_add_v4(float* p, float a, float b, float c, float d) {
    asm volatile("red.global.add.v4.f32 [%0], {%1, %2, %3, %4};"
                 :: "l"(p), "f"(a), "f"(b), "f"(c), "f"(d) : "memory");
}

__device__ __forceinline__ uint32_t cvt_tf32(float x) {
    uint32_t r; asm("cvt.rna.tf32.f32 %0, %1;" : "=r"(r) : "f"(x)); return r;
}

__device__ __forceinline__ void mma_tf32(float* c, const uint32_t* a, const uint32_t* b) {
    asm volatile("mma.sync.aligned.m16n8k8.row.col.f32.tf32.tf32.f32 "
                 "{%0,%1,%2,%3}, {%4,%5,%6,%7}, {%8,%9}, {%0,%1,%2,%3};"
                 : "+f"(c[0]), "+f"(c[1]), "+f"(c[2]), "+f"(c[3])
                 : "r"(a[0]), "r"(a[1]), "r"(a[2]), "r"(a[3]),
                   "r"(b[0]), "r"(b[1]));
}

// ---------------- temporal encoding: 256 edges per block, 8 warps x 32 edges ----------------
__device__ void temporal_body(int blk,
                              const float* __restrict__ delta_t,
                              const int* __restrict__ ei_src,
                              const float* __restrict__ Wt,
                              const float* __restrict__ bt,
                              const float* __restrict__ ln_g,
                              const float* __restrict__ ln_b)
{
    __shared__ float Wts[TDE * DD];
    __shared__ float bts[DD], gs[DD], bs[DD];
    __shared__ float tr[8][DD];
    for (int idx = threadIdx.x; idx < DD * TDE; idx += blockDim.x) {
        int j = idx / TDE, i = idx % TDE;
        Wts[i * DD + j] = Wt[idx];
    }
    for (int idx = threadIdx.x; idx < DD; idx += blockDim.x) {
        bts[idx] = bt[idx]; gs[idx] = ln_g[idx]; bs[idx] = ln_b[idx];
    }
    __syncthreads();

    int warp = threadIdx.x >> 5;
    int lane = threadIdx.x & 31;

    float freqs[8];
    #pragma unroll
    for (int m = 0; m < 8; m++)
        freqs[m] = exp2f(-(float)m * (9.965784284662087f / 8.0f));  // 1000^{-m/8}

    #pragma unroll 1
    for (int t = 0; t < 32; t++) {
        int w = blk * 256 + warp * 32 + t;
        if (w >= EE) break;

        float dt = delta_t[w];
        int src = ei_src[w];

        float sn[8], cn[8];
        #pragma unroll
        for (int m = 0; m < 8; m++) sincosf(dt * freqs[m], &sn[m], &cn[m]);

        float pt[8];
        float lsum = 0.0f;
        #pragma unroll
        for (int jj = 0; jj < 8; jj++) {
            int j = lane + jj * 32;
            float s = bts[j];
            #pragma unroll
            for (int m = 0; m < 8; m++)
                s += sn[m] * Wts[(2 * m) * DD + j] + cn[m] * Wts[(2 * m + 1) * DD + j];
            pt[jj] = s;
            lsum += s;
        }
        #pragma unroll
        for (int o = 16; o; o >>= 1) lsum += __shfl_xor_sync(0xffffffffu, lsum, o);
        float mu = lsum * (1.0f / 256.0f);

        float lvar = 0.0f;
        #pragma unroll
        for (int jj = 0; jj < 8; jj++) { float d = pt[jj] - mu; lvar += d * d; }
        #pragma unroll
        for (int o = 16; o; o >>= 1) lvar += __shfl_xor_sync(0xffffffffu, lvar, o);
        float rstd = rsqrtf(lvar * (1.0f / 256.0f) + 1e-5f);

        #pragma unroll
        for (int jj = 0; jj < 8; jj++) {
            int j = lane + jj * 32;
            tr[warp][j] = (pt[jj] - mu) * rstd * gs[j] + bs[j];
        }
        __syncwarp();
        float4 y0 = *(const float4*)&tr[warp][lane * 8];
        float4 y1 = *(const float4*)&tr[warp][lane * 8 + 4];
        float* xp = &g_xw[(size_t)src * DD + lane * 8];
        red_add_v4(xp,     y0.x, y0.y, y0.z, y0.w);
        red_add_v4(xp + 4, y1.x, y1.y, y1.z, y1.w);
        __syncwarp();
    }
}

// ---------------- launch 1: temporal + CSR count ----------------
__global__ void __launch_bounds__(256) fused_temporal_count(
    const float* __restrict__ delta_t,
    const int* __restrict__ e0, const int* __restrict__ e1,
    const int* __restrict__ e2, const int* __restrict__ e3,
    const float* __restrict__ Wt, const float* __restrict__ bt,
    const float* __restrict__ ln_g, const float* __restrict__ ln_b)
{
    int b = blockIdx.x;
    if (b < TEMP_BLOCKS) {
        temporal_body(b, delta_t, e0, Wt, bt, ln_g, ln_b);
    } else {
        int cb = b - TEMP_BLOCKS;
        int ty = cb / CNT_BPT;
        int i = (cb % CNT_BPT) * 256 + threadIdx.x;
        if (i < EE) {
            const int* ei = (ty == 0) ? e0 : (ty == 1) ? e1 : (ty == 2) ? e2 : e3;
            atomicAdd(&g_cur4[ty][ei[EE + i]], 1);
        }
    }
}

// ---------------- tensor-core 3xTF32 GEMM tile: 128x128, K=256, kchunk=16 ----------------
// C = A(N,256) @ W(256,256)^T + bias. 8 warps: 2(m) x 4(n), warp tile m64 x n32.
// smem layout: [row][k] padded to 20 floats per row -> fragment LDS conflict-free.
#define SMP 20

__device__ __forceinline__ void split_store(uint32_t* H, uint32_t* L, int idx, float4 v) {
    uint32_t h0 = cvt_tf32(v.x), h1 = cvt_tf32(v.y), h2 = cvt_tf32(v.z), h3 = cvt_tf32(v.w);
    uint32_t l0 = cvt_tf32(v.x - __uint_as_float(h0));
    uint32_t l1 = cvt_tf32(v.y - __uint_as_float(h1));
    uint32_t l2 = cvt_tf32(v.z - __uint_as_float(h2));
    uint32_t l3 = cvt_tf32(v.w - __uint_as_float(h3));
    *(uint4*)&H[idx] = make_uint4(h0, h1, h2, h3);
    *(uint4*)&L[idx] = make_uint4(l0, l1, l2, l3);
}

template <bool FUSE>
__device__ __forceinline__ void gemm_tile_tc(
    const float* __restrict__ A, const float* __restrict__ W,
    const float* __restrict__ bias, float* __restrict__ C, int N,
    const float* __restrict__ xsrc, float sa, int rowBase, int colBase)
{
    __shared__ uint32_t Ah[128 * SMP], Al[128 * SMP];
    __shared__ uint32_t Bh[128 * SMP], Bl[128 * SMP];

    int tid = threadIdx.x;
    int lane = tid & 31;
    int wid = tid >> 5;
    int mwarp = wid >> 2;      // 0..1
    int nwarp = wid & 3;       // 0..3
    int grp  = lane >> 2;      // 0..7
    int tid4 = lane & 3;       // 0..3

    int row0 = tid >> 2, q0 = (tid & 3) * 4;
    int row1 = row0 + 64;
    int gr0 = rowBase + row0, gr1 = rowBase + row1;
    int gc0 = colBase + row0, gc1 = colBase + row1;

    float acc[4][4][4];
    #pragma unroll
    for (int i = 0; i < 4; i++)
        #pragma unroll
        for (int j = 0; j < 4; j++)
            #pragma unroll
            for (int r = 0; r < 4; r++) acc[i][j][r] = 0.0f;

    for (int kt = 0; kt < 256; kt += 16) {
        float4 av0 = make_float4(0.f, 0.f, 0.f, 0.f);
        float4 av1 = make_float4(0.f, 0.f, 0.f, 0.f);
        if (gr0 < N) av0 = *(const float4*)(A + (size_t)gr0 * 256 + kt + q0);
        if (gr1 < N) av1 = *(const float4*)(A + (size_t)gr1 * 256 + kt + q0);
        if (FUSE) {
            av0.x = gelu_exact(av0.x); av0.y = gelu_exact(av0.y);
            av0.z = gelu_exact(av0.z); av0.w = gelu_exact(av0.w);
            av1.x = gelu_exact(av1.x); av1.y = gelu_exact(av1.y);
            av1.z = gelu_exact(av1.z); av1.w = gelu_exact(av1.w);
        }
        float4 bv0 = *(const float4*)(W + (size_t)gc0 * 256 + kt + q0);
        float4 bv1 = *(const float4*)(W + (size_t)gc1 * 256 + kt + q0);

        split_store(Ah, Al, row0 * SMP + q0, av0);
        split_store(Ah, Al, row1 * SMP + q0, av1);
        split_store(Bh, Bl, row0 * SMP + q0, bv0);
        split_store(Bh, Bl, row1 * SMP + q0, bv1);
        __syncthreads();

        #pragma unroll
        for (int s = 0; s < 2; s++) {
            int kb = s * 8 + tid4;
            uint32_t ah[4][4], al[4][4];
            #pragma unroll
            for (int mt = 0; mt < 4; mt++) {
                int base = (mwarp * 64 + mt * 16 + grp) * SMP + kb;
                ah[mt][0] = Ah[base];            al[mt][0] = Al[base];
                ah[mt][1] = Ah[base + 8 * SMP];  al[mt][1] = Al[base + 8 * SMP];
                ah[mt][2] = Ah[base + 4];        al[mt][2] = Al[base + 4];
                ah[mt][3] = Ah[base + 8 * SMP + 4]; al[mt][3] = Al[base + 8 * SMP + 4];
            }
            uint32_t bh[4][2], bl[4][2];
            #pragma unroll
            for (int nt = 0; nt < 4; nt++) {
                int base = (nwarp * 32 + nt * 8 + grp) * SMP + kb;
                bh[nt][0] = Bh[base];     bl[nt][0] = Bl[base];
                bh[nt][1] = Bh[base + 4]; bl[nt][1] = Bl[base + 4];
            }
            #pragma unroll
            for (int mt = 0; mt < 4; mt++)
                #pragma unroll
                for (int nt = 0; nt < 4; nt++) {
                    mma_tf32(acc[mt][nt], ah[mt], bh[nt]);
                    mma_tf32(acc[mt][nt], ah[mt], bl[nt]);
                    mma_tf32(acc[mt][nt], al[mt], bh[nt]);
                }
        }
        __syncthreads();
    }

    // epilogue
    #pragma unroll
    for (int mt = 0; mt < 4; mt++) {
        int r0g = rowBase + mwarp * 64 + mt * 16 + grp;
        int r1g = r0g + 8;
        #pragma unroll
        for (int nt = 0; nt < 4; nt++) {
            int c = colBase + nwarp * 32 + nt * 8 + tid4 * 2;
            float2 bi = *(const float2*)(bias + c);
            if (r0g < N) {
                float o0 = acc[mt][nt][0] + bi.x;
                float o1 = acc[mt][nt][1] + bi.y;
                if (FUSE) {
                    float2 xs = *(const float2*)(xsrc + (size_t)r0g * 256 + c);
                    o0 = sa * o0 + (1.0f - sa) * xs.x;
                    o1 = sa * o1 + (1.0f - sa) * xs.y;
                }
                *(float2*)(C + (size_t)r0g * 256 + c) = make_float2(o0, o1);
            }
            if (r1g < N) {
                float o2 = acc[mt][nt][2] + bi.x;
                float o3 = acc[mt][nt][3] + bi.y;
                if (FUSE) {
                    float2 xs = *(const float2*)(xsrc + (size_t)r1g * 256 + c);
                    o2 = sa * o2 + (1.0f - sa) * xs.x;
                    o3 = sa * o3 + (1.0f - sa) * xs.y;
                }
                *(float2*)(C + (size_t)r1g * 256 + c) = make_float2(o2, o3);
            }
        }
    }
}

// 256-thread exclusive scan of g_cur4[ty] -> g_off4[ty]; cur := offset
__device__ void csr_scan_body(int ty) {
    int Nd = (ty == 2) ? NMM : NOP;
    __shared__ int sp[256];
    int tid = threadIdx.x;
    int chunk = (Nd + 255) / 256;
    int beg = tid * chunk;
    int end = beg + chunk; if (end > Nd) end = Nd;
    int s = 0;
    for (int i = beg; i < end; i++) s += g_cur4[ty][i];
    sp[tid] = s;
    __syncthreads();
    #pragma unroll
    for (int o = 1; o < 256; o <<= 1) {
        int v = (tid >= o) ? sp[tid - o] : 0;
        __syncthreads();
        sp[tid] += v;
        __syncthreads();
    }
    int base = (tid == 0) ? 0 : sp[tid - 1];
    for (int i = beg; i < end; i++) {
        int d = g_cur4[ty][i];
        g_off4[ty][i] = base;
        g_cur4[ty][i] = base;
        base += d;
    }
    if (tid == 255) g_off4[ty][Nd] = sp[255];
}

// ---------------- launch 2: 6 k/q/v GEMMs + 4 CSR scans ----------------
__global__ void __launch_bounds__(256) fused_kqv_scan(
    const float* __restrict__ Aop, const float* __restrict__ Am,
    const float* __restrict__ Wk, const float* __restrict__ Wq, const float* __restrict__ Wv,
    const float* __restrict__ bk, const float* __restrict__ bq, const float* __restrict__ bv,
    float* __restrict__ kop, float* __restrict__ qop, float* __restrict__ vop,
    float* __restrict__ km,  float* __restrict__ qm,  float* __restrict__ vm)
{
    int b = blockIdx.x;
    if (b < 3 * TILES_ALL) {
        int z = b / TILES_ALL;
        int t = b % TILES_ALL;
        bool isM = t >= TILES_OP;
        int tt = isM ? t - TILES_OP : t;
        int rowBase = (tt >> 1) * 128;
        int colBase = (tt & 1) * 128;

        const float* A = isM ? Am : Aop;
        int N = isM ? NMM : NOP;
        const float* W = (z == 0 ? Wk : z == 1 ? Wq : Wv) + (isM ? DD * DD : 0);
        const float* bb = (z == 0 ? bk : z == 1 ? bq : bv) + (isM ? DD : 0);
        float* C = isM ? (z == 0 ? km : z == 1 ? qm : vm)
                       : (z == 0 ? kop : z == 1 ? qop : vop);
        gemm_tile_tc<false>(A, W, bb, C, N, nullptr, 0.0f, rowBase, colBase);
    } else {
        csr_scan_body(b - 3 * TILES_ALL);
    }
}

// ---------------- rel transform body ----------------
__device__ void rel_body(int e, int h, int xb,
                         const float* __restrict__ arel,
                         const float* __restrict__ mrel)
{
    int N = (e == 3) ? NMM : NOP;
    int nBase = xb * 64;
    if (nBase >= N) return;

    const float* ktab = (e == 3) ? g_k_m : g_k_op;
    const float* vtab = (e == 3) ? g_v_m : g_v_op;
    float* KT = (e == 3) ? g_KTm : g_KT[e];
    float* VT = (e == 3) ? g_VTm : g_VT[e];

    __shared__ float a_s[32 * 32], m_s[32 * 32];
    for (int i = threadIdx.x; i < 1024; i += 256) {
        a_s[i] = arel[((size_t)e * HH + h) * 1024 + i];
        m_s[i] = mrel[((size_t)e * HH + h) * 1024 + i];
    }
    __syncthreads();

    int warp = threadIdx.x >> 5, lane = threadIdx.x & 31;
    int n = nBase + warp * 8;
    #pragma unroll 1
    for (int t = 0; t < 8; t++, n++) {
        if (n >= N) break;
        float kv = ktab[(size_t)n * 256 + h * 32 + lane];
        float vv = vtab[(size_t)n * 256 + h * 32 + lane];
        float sk = 0.0f, sv = 0.0f;
        #pragma unroll
        for (int f = 0; f < 32; f++) {
            float kf = __shfl_sync(0xffffffffu, kv, f);
            float vf = __shfl_sync(0xffffffffu, vv, f);
            sk += kf * a_s[f * 32 + lane];
            sv += vf * m_s[f * 32 + lane];
        }
        KT[(size_t)n * 256 + h * 32 + lane] = sk;
        VT[(size_t)n * 256 + h * 32 + lane] = sv;
    }
}

// ---------------- launch 3: rel transforms + CSR fill ----------------
__global__ void __launch_bounds__(256) fused_rel_fill(
    const float* __restrict__ arel, const float* __restrict__ mrel,
    const int* __restrict__ e0, const int* __restrict__ e1,
    const int* __restrict__ e2, const int* __restrict__ e3)
{
    int b = blockIdx.x;
    if (b < REL_BLOCKS) {
        int e = b / (RELX * HH);
        int rem = b % (RELX * HH);
        int h = rem / RELX;
        int xb = rem % RELX;
        rel_body(e, h, xb, arel, mrel);
    } else {
        int cb = b - REL_BLOCKS;
        int ty = cb / CNT_BPT;
        int i = (cb % CNT_BPT) * 256 + threadIdx.x;
        if (i < EE) {
            const int* ei = (ty == 0) ? e0 : (ty == 1) ? e1 : (ty == 2) ? e2 : e3;
            int dst = ei[EE + i];
            int src = ei[i];
            int pos = atomicAdd(&g_cur4[ty][dst], 1);
            g_esrc4[ty][pos] = src;
        }
    }
}

// ---------------- gather bodies ----------------
__device__ void gather_op_body(int b, const float* __restrict__ prel)
{
    int w = b * 8 + (threadIdx.x >> 5);
    int lane = threadIdx.x & 31;
    if (w >= NOP) return;

    const float4* qp = (const float4*)(g_q_op + (size_t)w * 256);
    float4 q0 = qp[lane * 2], q1 = qp[lane * 2 + 1];
    int h = lane >> 2;

    float out[8] = {0.f, 0.f, 0.f, 0.f, 0.f, 0.f, 0.f, 0.f};

    #pragma unroll
    for (int pass = 0; pass < 3; pass++) {
        int e = (pass == 2) ? 3 : pass;
        const float* KT = (pass == 2) ? g_KTm : g_KT[e];
        const float* VT = (pass == 2) ? g_VTm : g_VT[e];
        float ps = prel[e * HH + h] * 0.17677669529663687f;   // 1/sqrt(32)

        int beg = g_off4[e][w], end = g_off4[e][w + 1];
        float num[8] = {0.f, 0.f, 0.f, 0.f, 0.f, 0.f, 0.f, 0.f};
        float den = 0.0f;
        #pragma unroll 2
        for (int j = beg; j < end; j++) {
            int src = g_esrc4[e][j];
            const float4* kp = (const float4*)(KT + (size_t)src * 256);
            const float4* vp = (const float4*)(VT + (size_t)src * 256);
            float4 k0 = kp[lane * 2], k1 = kp[lane * 2 + 1];
            float4 v0 = vp[lane * 2], v1 = vp[lane * 2 + 1];
            float s = q0.x * k0.x + q0.y * k0.y + q0.z * k0.z + q0.w * k0.w
                    + q1.x * k1.x + q1.y * k1.y + q1.z * k1.z + q1.w * k1.w;
            s += __shfl_xor_sync(0xffffffffu, s, 1);
            s += __shfl_xor_sync(0xffffffffu, s, 2);
            float ev = expf(s * ps);
            den += ev;
            num[0] += ev * v0.x; num[1] += ev * v0.y; num[2] += ev * v0.z; num[3] += ev * v0.w;
            num[4] += ev * v1.x; num[5] += ev * v1.y; num[6] += ev * v1.z; num[7] += ev * v1.w;
        }
        float inv = (den > 0.f) ? 1.0f / den : 0.0f;
        #pragma unroll
        for (int i = 0; i < 8; i++) out[i] += num[i] * inv;
    }

    float* ap = g_acc_op + (size_t)w * 256 + lane * 8;
    *(float4*)(ap)     = make_float4(out[0], out[1], out[2], out[3]);
    *(float4*)(ap + 4) = make_float4(out[4], out[5], out[6], out[7]);
}

__device__ void gather_m_body(int n, const float* __restrict__ prel)
{
    __shared__ float snum[8][256];
    __shared__ float sden[8][8];
    int warp = threadIdx.x >> 5, lane = threadIdx.x & 31;
    int h = lane >> 2;
    int beg = g_off4[2][n], end = g_off4[2][n + 1];

    const float4* qp = (const float4*)(g_q_m + (size_t)n * 256);
    float4 q0 = qp[lane * 2], q1 = qp[lane * 2 + 1];
    float ps = prel[2 * HH + h] * 0.17677669529663687f;

    float num[8] = {0.f, 0.f, 0.f, 0.f, 0.f, 0.f, 0.f, 0.f};
    float den = 0.0f;

    for (int j = beg + warp; j < end; j += 8) {
        int src = g_esrc4[2][j];
        const float4* kp = (const float4*)(g_KT[2] + (size_t)src * 256);
        const float4* vp = (const float4*)(g_VT[2] + (size_t)src * 256);
        float4 k0 = kp[lane * 2], k1 = kp[lane * 2 + 1];
        float4 v0 = vp[lane * 2], v1 = vp[lane * 2 + 1];
        float s = q0.x * k0.x + q0.y * k0.y + q0.z * k0.z + q0.w * k0.w
                + q1.x * k1.x + q1.y * k1.y + q1.z * k1.z + q1.w * k1.w;
        s += __shfl_xor_sync(0xffffffffu, s, 1);
        s += __shfl_xor_sync(0xffffffffu, s, 2);
        float ev = expf(s * ps);
        den += ev;
        num[0] += ev * v0.x; num[1] += ev * v0.y; num[2] += ev * v0.z; num[3] += ev * v0.w;
        num[4] += ev * v1.x; num[5] += ev * v1.y; num[6] += ev * v1.z; num[7] += ev * v1.w;
    }
    #pragma unroll
    for (int i = 0; i < 8; i += 4)
        *(float4*)&snum[warp][lane * 8 + i] = make_float4(num[i], num[i+1], num[i+2], num[i+3]);
    if ((lane & 3) == 0) sden[warp][h] = den;
    __syncthreads();

    {
        int c = threadIdx.x;
        float tot = 0.0f;
        #pragma unroll
        for (int ww = 0; ww < 8; ww++) tot += snum[ww][c];
        int hh = c >> 5;
        float d = 0.0f;
        #pragma unroll
        for (int ww = 0; ww < 8; ww++) d += sden[ww][hh];
        g_acc_m[(size_t)n * 256 + c] = (d > 0.f) ? tot / d : 0.0f;
    }
}

// ---------------- launch 4: both gathers ----------------
__global__ void __launch_bounds__(256) fused_gather(const float* __restrict__ prel)
{
    int b = blockIdx.x;
    if (b < GOP_BLOCKS) gather_op_body(b, prel);
    else                gather_m_body(b - GOP_BLOCKS, prel);
}

// ---------------- launch 5: both final FUSE GEMMs ----------------
__global__ void __launch_bounds__(256) gemm_final(
    const float* __restrict__ accop, const float* __restrict__ accm,
    const float* __restrict__ Wa, const float* __restrict__ ba,
    const float* __restrict__ xop, const float* __restrict__ xm,
    const float* __restrict__ skipv, float* __restrict__ out)
{
    int t = blockIdx.x;
    bool isM = t >= TILES_OP;
    int tt = isM ? t - TILES_OP : t;
    int rowBase = (tt >> 1) * 128;
    int colBase = (tt & 1) * 128;

    const float* A = isM ? accm : accop;
    int N = isM ? NMM : NOP;
    const float* W = Wa + (isM ? DD * DD : 0);
    const float* b = ba + (isM ? DD : 0);
    const float* xs = isM ? xm : xop;
    float* C = out + (isM ? (size_t)NOP * DD : 0);
    float sa = 1.0f / (1.0f + expf(-skipv[isM ? 1 : 0]));

    gemm_tile_tc<true>(A, W, b, C, N, xs, sa, rowBase, colBase);
}

// ---------------- host side ----------------
static float* symaddr(const void* sym) {
    void* p = nullptr;
    cudaGetSymbolAddress(&p, sym);
    return (float*)p;
}

extern "C" void kernel_launch(void* const* d_in, const int* in_sizes, int n_in,
                              void* d_out, int out_size)
{
    const float* x_op    = (const float*)d_in[0];
    const float* x_m     = (const float*)d_in[1];
    const float* delta_t = (const float*)d_in[2];
    const int*   ei0 = (const int*)d_in[3];
    const int*   ei1 = (const int*)d_in[4];
    const int*   ei2 = (const int*)d_in[5];
    const int*   ei3 = (const int*)d_in[6];
    const float* Wt   = (const float*)d_in[7];
    const float* bt   = (const float*)d_in[8];
    const float* ln_g = (const float*)d_in[9];
    const float* ln_b = (const float*)d_in[10];
    const float* Wk   = (const float*)d_in[11];
    const float* bk   = (const float*)d_in[12];
    const float* Wq   = (const float*)d_in[13];
    const float* bq   = (const float*)d_in[14];
    const float* Wv   = (const float*)d_in[15];
    const float* bv   = (const float*)d_in[16];
    const float* Wa   = (const float*)d_in[17];
    const float* ba   = (const float*)d_in[18];
    const float* skip = (const float*)d_in[19];
    const float* a_rel = (const float*)d_in[20];
    const float* m_rel = (const float*)d_in[21];
    const float* p_rel = (const float*)d_in[22];
    float* out = (float*)d_out;

    float* xw    = symaddr(g_xw);
    float* k_op  = symaddr(g_k_op);
    float* q_op  = symaddr(g_q_op);
    float* v_op  = symaddr(g_v_op);
    float* k_m   = symaddr(g_k_m);
    float* q_m   = symaddr(g_q_m);
    float* v_m   = symaddr(g_v_m);
    float* acc_op = symaddr(g_acc_op);
    float* acc_m  = symaddr(g_acc_m);
    int*   cur4  = (int*)symaddr(g_cur4);

    cudaMemcpyAsync(xw, x_op, (size_t)NOP * DD * sizeof(float), cudaMemcpyDeviceToDevice);
    cudaMemsetAsync(cur4, 0, (size_t)4 * NOP * sizeof(int));

    // L1: temporal encoding + CSR degree count
    fused_temporal_count<<<TEMP_BLOCKS + 4 * CNT_BPT, 256>>>(
        delta_t, ei0, ei1, ei2, ei3, Wt, bt, ln_g, ln_b);

    // L2: 6 k/q/v GEMMs (tensor core 3xTF32) + 4 CSR scans
    fused_kqv_scan<<<3 * TILES_ALL + 4, 256>>>(
        xw, x_m, Wk, Wq, Wv, bk, bq, bv,
        k_op, q_op, v_op, k_m, q_m, v_m);

    // L3: relation transforms + CSR fill
    fused_rel_fill<<<REL_BLOCKS + 4 * CNT_BPT, 256>>>(a_rel, m_rel, ei0, ei1, ei2, ei3);

    // L4: both gathers
    fused_gather<<<GOP_BLOCKS + NMM, 256>>>(p_rel);

    // L5: both final GEMMs (tensor core)
    gemm_final<<<TILES_ALL, 256>>>(acc_op, acc_m, Wa, ba, xw, x_m, skip, out);
}

// round 12
// speedup vs baseline: 3.1796x; 1.1653x over previous
#include <cuda_runtime.h>
#include <math.h>
#include <stdint.h>

#define NOP 20000
#define NMM 500
#define DD  256
#define HH  8
#define DHD 32
#define TDE 16
#define EE  200000

#define TILES_OP 314   // 157 rowblocks x 2 colblocks
#define TILES_M  8     // 4 x 2
#define TILES_ALL (TILES_OP + TILES_M)

#define TEMP_BLOCKS 782            // ceil(EE/256), 256 edges per block
#define CNT_BPT 782                // count blocks per edge type: ceil(EE/256)
#define RELB_PER_H 313             // ceil(NOP/64) node-blocks per (type<3, head)
#define RELB_OP (RELB_PER_H * HH)  // 2504 per op-src type
#define RELB_M_PER_H 8             // ceil(NMM/64)
#define REL_TC (3 * RELB_OP + RELB_M_PER_H * HH)   // 7576
#define GOP_BLOCKS 2500            // NOP*32/256

// ---------------- scratch ----------------
__device__ float g_xw[NOP * DD];
__device__ float g_k_op[NOP * DD];
__device__ float g_q_op[NOP * DD];
__device__ float g_v_op[NOP * DD];
__device__ float g_k_m[NMM * DD];
__device__ float g_q_m[NMM * DD];
__device__ float g_v_m[NMM * DD];
__device__ float g_KT[3][NOP * DD];
__device__ float g_VT[3][NOP * DD];
__device__ float g_KTm[NMM * DD];
__device__ float g_VTm[NMM * DD];
__device__ float g_acc_op[NOP * DD];
__device__ float g_acc_m[NMM * DD];
__device__ int   g_off4[4][NOP + 1];
__device__ int   g_cur4[4][NOP];
__device__ int   g_esrc4[4][EE];

__device__ __forceinline__ float gelu_exact(float x) {
    return 0.5f * x * (1.0f + erff(x * 0.70710678118654752f));
}

__device__ __forceinline__ void red_add_v4(float* p, float a, float b, float c, float d) {
    asm volatile("red.global.add.v4.f32 [%0], {%1, %2, %3, %4};"
                 :: "l"(p), "f"(a), "f"(b), "f"(c), "f"(d) : "memory");
}

__device__ __forceinline__ uint32_t cvt_tf32(float x) {
    uint32_t r; asm("cvt.rna.tf32.f32 %0, %1;" : "=r"(r) : "f"(x)); return r;
}

__device__ __forceinline__ void mma_tf32(float* c, const uint32_t* a, const uint32_t* b) {
    asm volatile("mma.sync.aligned.m16n8k8.row.col.f32.tf32.tf32.f32 "
                 "{%0,%1,%2,%3}, {%4,%5,%6,%7}, {%8,%9}, {%0,%1,%2,%3};"
                 : "+f"(c[0]), "+f"(c[1]), "+f"(c[2]), "+f"(c[3])
                 : "r"(a[0]), "r"(a[1]), "r"(a[2]), "r"(a[3]),
                   "r"(b[0]), "r"(b[1]));
}

// ---------------- temporal encoding: 256 edges per block, 8 warps x 32 edges ----------------
__device__ void temporal_body(int blk,
                              const float* __restrict__ delta_t,
                              const int* __restrict__ ei_src,
                              const float* __restrict__ Wt,
                              const float* __restrict__ bt,
                              const float* __restrict__ ln_g,
                              const float* __restrict__ ln_b)
{
    __shared__ float Wts[TDE * DD];
    __shared__ float bts[DD], gs[DD], bs[DD];
    __shared__ float tr[8][DD];
    for (int idx = threadIdx.x; idx < DD * TDE; idx += blockDim.x) {
        int j = idx / TDE, i = idx % TDE;
        Wts[i * DD + j] = Wt[idx];
    }
    for (int idx = threadIdx.x; idx < DD; idx += blockDim.x) {
        bts[idx] = bt[idx]; gs[idx] = ln_g[idx]; bs[idx] = ln_b[idx];
    }
    __syncthreads();

    int warp = threadIdx.x >> 5;
    int lane = threadIdx.x & 31;

    float freqs[8];
    #pragma unroll
    for (int m = 0; m < 8; m++)
        freqs[m] = exp2f(-(float)m * (9.965784284662087f / 8.0f));  // 1000^{-m/8}

    #pragma unroll 1
    for (int t = 0; t < 32; t++) {
        int w = blk * 256 + warp * 32 + t;
        if (w >= EE) break;

        float dt = delta_t[w];
        int src = ei_src[w];

        float sn[8], cn[8];
        #pragma unroll
        for (int m = 0; m < 8; m++) sincosf(dt * freqs[m], &sn[m], &cn[m]);

        float pt[8];
        float lsum = 0.0f;
        #pragma unroll
        for (int jj = 0; jj < 8; jj++) {
            int j = lane + jj * 32;
            float s = bts[j];
            #pragma unroll
            for (int m = 0; m < 8; m++)
                s += sn[m] * Wts[(2 * m) * DD + j] + cn[m] * Wts[(2 * m + 1) * DD + j];
            pt[jj] = s;
            lsum += s;
        }
        #pragma unroll
        for (int o = 16; o; o >>= 1) lsum += __shfl_xor_sync(0xffffffffu, lsum, o);
        float mu = lsum * (1.0f / 256.0f);

        float lvar = 0.0f;
        #pragma unroll
        for (int jj = 0; jj < 8; jj++) { float d = pt[jj] - mu; lvar += d * d; }
        #pragma unroll
        for (int o = 16; o; o >>= 1) lvar += __shfl_xor_sync(0xffffffffu, lvar, o);
        float rstd = rsqrtf(lvar * (1.0f / 256.0f) + 1e-5f);

        #pragma unroll
        for (int jj = 0; jj < 8; jj++) {
            int j = lane + jj * 32;
            tr[warp][j] = (pt[jj] - mu) * rstd * gs[j] + bs[j];
        }
        __syncwarp();
        float4 y0 = *(const float4*)&tr[warp][lane * 8];
        float4 y1 = *(const float4*)&tr[warp][lane * 8 + 4];
        float* xp = &g_xw[(size_t)src * DD + lane * 8];
        red_add_v4(xp,     y0.x, y0.y, y0.z, y0.w);
        red_add_v4(xp + 4, y1.x, y1.y, y1.z, y1.w);
        __syncwarp();
    }
}

// ---------------- launch 1: temporal + CSR count ----------------
__global__ void __launch_bounds__(256) fused_temporal_count(
    const float* __restrict__ delta_t,
    const int* __restrict__ e0, const int* __restrict__ e1,
    const int* __restrict__ e2, const int* __restrict__ e3,
    const float* __restrict__ Wt, const float* __restrict__ bt,
    const float* __restrict__ ln_g, const float* __restrict__ ln_b)
{
    int b = blockIdx.x;
    if (b < TEMP_BLOCKS) {
        temporal_body(b, delta_t, e0, Wt, bt, ln_g, ln_b);
    } else {
        int cb = b - TEMP_BLOCKS;
        int ty = cb / CNT_BPT;
        int i = (cb % CNT_BPT) * 256 + threadIdx.x;
        if (i < EE) {
            const int* ei = (ty == 0) ? e0 : (ty == 1) ? e1 : (ty == 2) ? e2 : e3;
            atomicAdd(&g_cur4[ty][ei[EE + i]], 1);
        }
    }
}

// ---------------- tensor-core 3xTF32 GEMM tile: 128x128, K=256, pipelined ----------------
#define SMP 20

__device__ __forceinline__ void split_store(uint32_t* H, uint32_t* L, int idx, float4 v) {
    uint32_t h0 = cvt_tf32(v.x), h1 = cvt_tf32(v.y), h2 = cvt_tf32(v.z), h3 = cvt_tf32(v.w);
    uint32_t l0 = cvt_tf32(v.x - __uint_as_float(h0));
    uint32_t l1 = cvt_tf32(v.y - __uint_as_float(h1));
    uint32_t l2 = cvt_tf32(v.z - __uint_as_float(h2));
    uint32_t l3 = cvt_tf32(v.w - __uint_as_float(h3));
    *(uint4*)&H[idx] = make_uint4(h0, h1, h2, h3);
    *(uint4*)&L[idx] = make_uint4(l0, l1, l2, l3);
}

template <bool FUSE>
__device__ __forceinline__ void gemm_tile_tc(
    const float* __restrict__ A, const float* __restrict__ W,
    const float* __restrict__ bias, float* __restrict__ C, int N,
    const float* __restrict__ xsrc, float sa, int rowBase, int colBase)
{
    __shared__ uint32_t Ah[128 * SMP], Al[128 * SMP];
    __shared__ uint32_t Bh[128 * SMP], Bl[128 * SMP];

    int tid = threadIdx.x;
    int lane = tid & 31;
    int wid = tid >> 5;
    int mwarp = wid >> 2;
    int nwarp = wid & 3;
    int grp  = lane >> 2;
    int tid4 = lane & 3;

    int row0 = tid >> 2, q0 = (tid & 3) * 4;
    int row1 = row0 + 64;
    int gr0 = rowBase + row0, gr1 = rowBase + row1;
    int gc0 = colBase + row0, gc1 = colBase + row1;

    float acc[4][4][4];
    #pragma unroll
    for (int i = 0; i < 4; i++)
        #pragma unroll
        for (int j = 0; j < 4; j++)
            #pragma unroll
            for (int r = 0; r < 4; r++) acc[i][j][r] = 0.0f;

    float4 av0, av1, bv0, bv1;
    auto ldg = [&](int kt) {
        av0 = make_float4(0.f, 0.f, 0.f, 0.f);
        av1 = make_float4(0.f, 0.f, 0.f, 0.f);
        if (gr0 < N) av0 = *(const float4*)(A + (size_t)gr0 * 256 + kt + q0);
        if (gr1 < N) av1 = *(const float4*)(A + (size_t)gr1 * 256 + kt + q0);
        if (FUSE) {
            av0.x = gelu_exact(av0.x); av0.y = gelu_exact(av0.y);
            av0.z = gelu_exact(av0.z); av0.w = gelu_exact(av0.w);
            av1.x = gelu_exact(av1.x); av1.y = gelu_exact(av1.y);
            av1.z = gelu_exact(av1.z); av1.w = gelu_exact(av1.w);
        }
        bv0 = *(const float4*)(W + (size_t)gc0 * 256 + kt + q0);
        bv1 = *(const float4*)(W + (size_t)gc1 * 256 + kt + q0);
    };
    auto sts = [&]() {
        split_store(Ah, Al, row0 * SMP + q0, av0);
        split_store(Ah, Al, row1 * SMP + q0, av1);
        split_store(Bh, Bl, row0 * SMP + q0, bv0);
        split_store(Bh, Bl, row1 * SMP + q0, bv1);
    };

    ldg(0);
    sts();
    __syncthreads();

    for (int it = 0; it < 16; it++) {
        if (it < 15) ldg((it + 1) * 16);   // prefetch hides under mma

        #pragma unroll
        for (int s = 0; s < 2; s++) {
            int kb = s * 8 + tid4;
            uint32_t ah[4][4], al[4][4];
            #pragma unroll
            for (int mt = 0; mt < 4; mt++) {
                int base = (mwarp * 64 + mt * 16 + grp) * SMP + kb;
                ah[mt][0] = Ah[base];            al[mt][0] = Al[base];
                ah[mt][1] = Ah[base + 8 * SMP];  al[mt][1] = Al[base + 8 * SMP];
                ah[mt][2] = Ah[base + 4];        al[mt][2] = Al[base + 4];
                ah[mt][3] = Ah[base + 8 * SMP + 4]; al[mt][3] = Al[base + 8 * SMP + 4];
            }
            uint32_t bh[4][2], bl[4][2];
            #pragma unroll
            for (int nt = 0; nt < 4; nt++) {
                int base = (nwarp * 32 + nt * 8 + grp) * SMP + kb;
                bh[nt][0] = Bh[base];     bl[nt][0] = Bl[base];
                bh[nt][1] = Bh[base + 4]; bl[nt][1] = Bl[base + 4];
            }
            #pragma unroll
            for (int mt = 0; mt < 4; mt++)
                #pragma unroll
                for (int nt = 0; nt < 4; nt++) {
                    mma_tf32(acc[mt][nt], ah[mt], bh[nt]);
                    mma_tf32(acc[mt][nt], ah[mt], bl[nt]);
                    mma_tf32(acc[mt][nt], al[mt], bh[nt]);
                }
        }
        __syncthreads();
        if (it < 15) {
            sts();
            __syncthreads();
        }
    }

    #pragma unroll
    for (int mt = 0; mt < 4; mt++) {
        int r0g = rowBase + mwarp * 64 + mt * 16 + grp;
        int r1g = r0g + 8;
        #pragma unroll
        for (int nt = 0; nt < 4; nt++) {
            int c = colBase + nwarp * 32 + nt * 8 + tid4 * 2;
            float2 bi = *(const float2*)(bias + c);
            if (r0g < N) {
                float o0 = acc[mt][nt][0] + bi.x;
                float o1 = acc[mt][nt][1] + bi.y;
                if (FUSE) {
                    float2 xs = *(const float2*)(xsrc + (size_t)r0g * 256 + c);
                    o0 = sa * o0 + (1.0f - sa) * xs.x;
                    o1 = sa * o1 + (1.0f - sa) * xs.y;
                }
                *(float2*)(C + (size_t)r0g * 256 + c) = make_float2(o0, o1);
            }
            if (r1g < N) {
                float o2 = acc[mt][nt][2] + bi.x;
                float o3 = acc[mt][nt][3] + bi.y;
                if (FUSE) {
                    float2 xs = *(const float2*)(xsrc + (size_t)r1g * 256 + c);
                    o2 = sa * o2 + (1.0f - sa) * xs.x;
                    o3 = sa * o3 + (1.0f - sa) * xs.y;
                }
                *(float2*)(C + (size_t)r1g * 256 + c) = make_float2(o2, o3);
            }
        }
    }
}

// 256-thread exclusive scan of g_cur4[ty] -> g_off4[ty]; cur := offset
__device__ void csr_scan_body(int ty) {
    int Nd = (ty == 2) ? NMM : NOP;
    __shared__ int sp[256];
    int tid = threadIdx.x;
    int chunk = (Nd + 255) / 256;
    int beg = tid * chunk;
    int end = beg + chunk; if (end > Nd) end = Nd;
    int s = 0;
    for (int i = beg; i < end; i++) s += g_cur4[ty][i];
    sp[tid] = s;
    __syncthreads();
    #pragma unroll
    for (int o = 1; o < 256; o <<= 1) {
        int v = (tid >= o) ? sp[tid - o] : 0;
        __syncthreads();
        sp[tid] += v;
        __syncthreads();
    }
    int base = (tid == 0) ? 0 : sp[tid - 1];
    for (int i = beg; i < end; i++) {
        int d = g_cur4[ty][i];
        g_off4[ty][i] = base;
        g_cur4[ty][i] = base;
        base += d;
    }
    if (tid == 255) g_off4[ty][Nd] = sp[255];
}

// ---------------- launch 2: 6 k/q/v GEMMs + 4 CSR scans ----------------
__global__ void __launch_bounds__(256) fused_kqv_scan(
    const float* __restrict__ Aop, const float* __restrict__ Am,
    const float* __restrict__ Wk, const float* __restrict__ Wq, const float* __restrict__ Wv,
    const float* __restrict__ bk, const float* __restrict__ bq, const float* __restrict__ bv,
    float* __restrict__ kop, float* __restrict__ qop, float* __restrict__ vop,
    float* __restrict__ km,  float* __restrict__ qm,  float* __restrict__ vm)
{
    int b = blockIdx.x;
    if (b < 3 * TILES_ALL) {
        int z = b / TILES_ALL;
        int t = b % TILES_ALL;
        bool isM = t >= TILES_OP;
        int tt = isM ? t - TILES_OP : t;
        int rowBase = (tt >> 1) * 128;
        int colBase = (tt & 1) * 128;

        const float* A = isM ? Am : Aop;
        int N = isM ? NMM : NOP;
        const float* W = (z == 0 ? Wk : z == 1 ? Wq : Wv) + (isM ? DD * DD : 0);
        const float* bb = (z == 0 ? bk : z == 1 ? bq : bv) + (isM ? DD : 0);
        float* C = isM ? (z == 0 ? km : z == 1 ? qm : vm)
                       : (z == 0 ? kop : z == 1 ? qop : vop);
        gemm_tile_tc<false>(A, W, bb, C, N, nullptr, 0.0f, rowBase, colBase);
    } else {
        csr_scan_body(b - 3 * TILES_ALL);
    }
}

// ---------------- tensor-core rel transform: [64 x 32] @ [32 x 32] per (e,h) block ----------------
// K̃[n,f] = sum_d k[n,h*32+d] * a_rel[e,h,d,f]  (B loaded transposed: Bsmem[f][d])
__device__ void rel_body_tc(int e, int h, int xb,
                            const float* __restrict__ arel,
                            const float* __restrict__ mrel)
{
    int N = (e == 3) ? NMM : NOP;
    int nBase = xb * 64;
    if (nBase >= N) return;

    const float* ktab = (e == 3) ? g_k_m : g_k_op;
    const float* vtab = (e == 3) ? g_v_m : g_v_op;
    float* KT = (e == 3) ? g_KTm : g_KT[e];
    float* VT = (e == 3) ? g_VTm : g_VT[e];

    __shared__ uint32_t Ah[64 * 36], Al[64 * 36];
    __shared__ uint32_t Bah[32 * 36], Bal[32 * 36], Bmh[32 * 36], Bml[32 * 36];

    int tid = threadIdx.x, lane = tid & 31, wid = tid >> 5;
    int grp = lane >> 2, tid4 = lane & 3;
    int mt = wid & 3;             // m-tile (16 rows) within 64
    int ntbase = (wid >> 2) * 2;  // 2 n-tiles of 8 per warp

    // load both relation matrices (transposed) with hi/lo split
    for (int i = tid; i < 1024; i += 256) {
        int d = i >> 5, f = i & 31;
        float va = arel[((size_t)(e * HH + h)) * 1024 + i];
        float vm = mrel[((size_t)(e * HH + h)) * 1024 + i];
        uint32_t hh = cvt_tf32(va);
        Bah[f * 36 + d] = hh;
        Bal[f * 36 + d] = cvt_tf32(va - __uint_as_float(hh));
        hh = cvt_tf32(vm);
        Bmh[f * 36 + d] = hh;
        Bml[f * 36 + d] = cvt_tf32(vm - __uint_as_float(hh));
    }

    #pragma unroll
    for (int phase = 0; phase < 2; phase++) {
        const float* xt = phase ? vtab : ktab;
        __syncthreads();   // phase0: B stores done; phase1: prior mma reads done before A overwrite
        for (int q = tid; q < 512; q += 256) {
            int r = q >> 3, c4 = (q & 7) * 4;
            float4 v = make_float4(0.f, 0.f, 0.f, 0.f);
            if (nBase + r < N)
                v = *(const float4*)(xt + (size_t)(nBase + r) * 256 + h * 32 + c4);
            uint32_t h0 = cvt_tf32(v.x), h1 = cvt_tf32(v.y), h2 = cvt_tf32(v.z), h3 = cvt_tf32(v.w);
            int idx = r * 36 + c4;
            Ah[idx] = h0; Ah[idx + 1] = h1; Ah[idx + 2] = h2; Ah[idx + 3] = h3;
            Al[idx]     = cvt_tf32(v.x - __uint_as_float(h0));
            Al[idx + 1] = cvt_tf32(v.y - __uint_as_float(h1));
            Al[idx + 2] = cvt_tf32(v.z - __uint_as_float(h2));
            Al[idx + 3] = cvt_tf32(v.w - __uint_as_float(h3));
        }
        __syncthreads();

        const uint32_t* Bh = phase ? Bmh : Bah;
        const uint32_t* Bl = phase ? Bml : Bal;
        float acc[2][4];
        #pragma unroll
        for (int j = 0; j < 2; j++)
            #pragma unroll
            for (int r = 0; r < 4; r++) acc[j][r] = 0.0f;

        #pragma unroll
        for (int kc = 0; kc < 4; kc++) {
            int kb = kc * 8 + tid4;
            int ab = (mt * 16 + grp) * 36 + kb;
            uint32_t ah[4] = {Ah[ab], Ah[ab + 8 * 36], Ah[ab + 4], Ah[ab + 8 * 36 + 4]};
            uint32_t al[4] = {Al[ab], Al[ab + 8 * 36], Al[ab + 4], Al[ab + 8 * 36 + 4]};
            #pragma unroll
            for (int j = 0; j < 2; j++) {
                int bb = ((ntbase + j) * 8 + grp) * 36 + kb;
                uint32_t bh[2] = {Bh[bb], Bh[bb + 4]};
                uint32_t bl[2] = {Bl[bb], Bl[bb + 4]};
                mma_tf32(acc[j], ah, bh);
                mma_tf32(acc[j], ah, bl);
                mma_tf32(acc[j], al, bh);
            }
        }

        float* OUT = phase ? VT : KT;
        int r0 = nBase + mt * 16 + grp;
        int r1 = r0 + 8;
        #pragma unroll
        for (int j = 0; j < 2; j++) {
            int c = (ntbase + j) * 8 + tid4 * 2;
            if (r0 < N)
                *(float2*)(OUT + (size_t)r0 * 256 + h * 32 + c) = make_float2(acc[j][0], acc[j][1]);
            if (r1 < N)
                *(float2*)(OUT + (size_t)r1 * 256 + h * 32 + c) = make_float2(acc[j][2], acc[j][3]);
        }
    }
}

// ---------------- launch 3: rel transforms (TC) + CSR fill ----------------
__global__ void __launch_bounds__(256) fused_rel_fill(
    const float* __restrict__ arel, const float* __restrict__ mrel,
    const int* __restrict__ e0, const int* __restrict__ e1,
    const int* __restrict__ e2, const int* __restrict__ e3)
{
    int b = blockIdx.x;
    if (b < 3 * RELB_OP) {
        int e = b / RELB_OP;
        int rem = b % RELB_OP;
        int h = rem / RELB_PER_H;
        int xb = rem % RELB_PER_H;
        rel_body_tc(e, h, xb, arel, mrel);
    } else if (b < REL_TC) {
        int b2 = b - 3 * RELB_OP;
        int h = b2 / RELB_M_PER_H;
        int xb = b2 % RELB_M_PER_H;
        rel_body_tc(3, h, xb, arel, mrel);
    } else {
        int cb = b - REL_TC;
        int ty = cb / CNT_BPT;
        int i = (cb % CNT_BPT) * 256 + threadIdx.x;
        if (i < EE) {
            const int* ei = (ty == 0) ? e0 : (ty == 1) ? e1 : (ty == 2) ? e2 : e3;
            int dst = ei[EE + i];
            int src = ei[i];
            int pos = atomicAdd(&g_cur4[ty][dst], 1);
            g_esrc4[ty][pos] = src;
        }
    }
}

// ---------------- gather bodies ----------------
__device__ void gather_op_body(int b, const float* __restrict__ prel)
{
    int w = b * 8 + (threadIdx.x >> 5);
    int lane = threadIdx.x & 31;
    if (w >= NOP) return;

    const float4* qp = (const float4*)(g_q_op + (size_t)w * 256);
    float4 q0 = qp[lane * 2], q1 = qp[lane * 2 + 1];
    int h = lane >> 2;

    float out[8] = {0.f, 0.f, 0.f, 0.f, 0.f, 0.f, 0.f, 0.f};

    #pragma unroll
    for (int pass = 0; pass < 3; pass++) {
        int e = (pass == 2) ? 3 : pass;
        const float* KT = (pass == 2) ? g_KTm : g_KT[e];
        const float* VT = (pass == 2) ? g_VTm : g_VT[e];
        float ps = prel[e * HH + h] * 0.17677669529663687f;   // 1/sqrt(32)

        int beg = g_off4[e][w], end = g_off4[e][w + 1];
        float num[8] = {0.f, 0.f, 0.f, 0.f, 0.f, 0.f, 0.f, 0.f};
        float den = 0.0f;
        #pragma unroll 2
        for (int j = beg; j < end; j++) {
            int src = g_esrc4[e][j];
            const float4* kp = (const float4*)(KT + (size_t)src * 256);
            const float4* vp = (const float4*)(VT + (size_t)src * 256);
            float4 k0 = kp[lane * 2], k1 = kp[lane * 2 + 1];
            float4 v0 = vp[lane * 2], v1 = vp[lane * 2 + 1];
            float s = q0.x * k0.x + q0.y * k0.y + q0.z * k0.z + q0.w * k0.w
                    + q1.x * k1.x + q1.y * k1.y + q1.z * k1.z + q1.w * k1.w;
            s += __shfl_xor_sync(0xffffffffu, s, 1);
            s += __shfl_xor_sync(0xffffffffu, s, 2);
            float ev = expf(s * ps);
            den += ev;
            num[0] += ev * v0.x; num[1] += ev * v0.y; num[2] += ev * v0.z; num[3] += ev * v0.w;
            num[4] += ev * v1.x; num[5] += ev * v1.y; num[6] += ev * v1.z; num[7] += ev * v1.w;
        }
        float inv = (den > 0.f) ? 1.0f / den : 0.0f;
        #pragma unroll
        for (int i = 0; i < 8; i++) out[i] += num[i] * inv;
    }

    float* ap = g_acc_op + (size_t)w * 256 + lane * 8;
    *(float4*)(ap)     = make_float4(out[0], out[1], out[2], out[3]);
    *(float4*)(ap + 4) = make_float4(out[4], out[5], out[6], out[7]);
}

__device__ void gather_m_body(int n, const float* __restrict__ prel)
{
    __shared__ float snum[8][256];
    __shared__ float sden[8][8];
    int warp = threadIdx.x >> 5, lane = threadIdx.x & 31;
    int h = lane >> 2;
    int beg = g_off4[2][n], end = g_off4[2][n + 1];

    const float4* qp = (const float4*)(g_q_m + (size_t)n * 256);
    float4 q0 = qp[lane * 2], q1 = qp[lane * 2 + 1];
    float ps = prel[2 * HH + h] * 0.17677669529663687f;

    float num[8] = {0.f, 0.f, 0.f, 0.f, 0.f, 0.f, 0.f, 0.f};
    float den = 0.0f;

    for (int j = beg + warp; j < end; j += 8) {
        int src = g_esrc4[2][j];
        const float4* kp = (const float4*)(g_KT[2] + (size_t)src * 256);
        const float4* vp = (const float4*)(g_VT[2] + (size_t)src * 256);
        float4 k0 = kp[lane * 2], k1 = kp[lane * 2 + 1];
        float4 v0 = vp[lane * 2], v1 = vp[lane * 2 + 1];
        float s = q0.x * k0.x + q0.y * k0.y + q0.z * k0.z + q0.w * k0.w
                + q1.x * k1.x + q1.y * k1.y + q1.z * k1.z + q1.w * k1.w;
        s += __shfl_xor_sync(0xffffffffu, s, 1);
        s += __shfl_xor_sync(0xffffffffu, s, 2);
        float ev = expf(s * ps);
        den += ev;
        num[0] += ev * v0.x; num[1] += ev * v0.y; num[2] += ev * v0.z; num[3] += ev * v0.w;
        num[4] += ev * v1.x; num[5] += ev * v1.y; num[6] += ev * v1.z; num[7] += ev * v1.w;
    }
    #pragma unroll
    for (int i = 0; i < 8; i += 4)
        *(float4*)&snum[warp][lane * 8 + i] = make_float4(num[i], num[i+1], num[i+2], num[i+3]);
    if ((lane & 3) == 0) sden[warp][h] = den;
    __syncthreads();

    {
        int c = threadIdx.x;
        float tot = 0.0f;
        #pragma unroll
        for (int ww = 0; ww < 8; ww++) tot += snum[ww][c];
        int hh = c >> 5;
        float d = 0.0f;
        #pragma unroll
        for (int ww = 0; ww < 8; ww++) d += sden[ww][hh];
        g_acc_m[(size_t)n * 256 + c] = (d > 0.f) ? tot / d : 0.0f;
    }
}

// ---------------- launch 4: both gathers ----------------
__global__ void __launch_bounds__(256) fused_gather(const float* __restrict__ prel)
{
    int b = blockIdx.x;
    if (b < GOP_BLOCKS) gather_op_body(b, prel);
    else                gather_m_body(b - GOP_BLOCKS, prel);
}

// ---------------- launch 5: both final FUSE GEMMs ----------------
__global__ void __launch_bounds__(256) gemm_final(
    const float* __restrict__ accop, const float* __restrict__ accm,
    const float* __restrict__ Wa, const float* __restrict__ ba,
    const float* __restrict__ xop, const float* __restrict__ xm,
    const float* __restrict__ skipv, float* __restrict__ out)
{
    int t = blockIdx.x;
    bool isM = t >= TILES_OP;
    int tt = isM ? t - TILES_OP : t;
    int rowBase = (tt >> 1) * 128;
    int colBase = (tt & 1) * 128;

    const float* A = isM ? accm : accop;
    int N = isM ? NMM : NOP;
    const float* W = Wa + (isM ? DD * DD : 0);
    const float* b = ba + (isM ? DD : 0);
    const float* xs = isM ? xm : xop;
    float* C = out + (isM ? (size_t)NOP * DD : 0);
    float sa = 1.0f / (1.0f + expf(-skipv[isM ? 1 : 0]));

    gemm_tile_tc<true>(A, W, b, C, N, xs, sa, rowBase, colBase);
}

// ---------------- host side ----------------
static float* symaddr(const void* sym) {
    void* p = nullptr;
    cudaGetSymbolAddress(&p, sym);
    return (float*)p;
}

extern "C" void kernel_launch(void* const* d_in, const int* in_sizes, int n_in,
                              void* d_out, int out_size)
{
    const float* x_op    = (const float*)d_in[0];
    const float* x_m     = (const float*)d_in[1];
    const float* delta_t = (const float*)d_in[2];
    const int*   ei0 = (const int*)d_in[3];
    const int*   ei1 = (const int*)d_in[4];
    const int*   ei2 = (const int*)d_in[5];
    const int*   ei3 = (const int*)d_in[6];
    const float* Wt   = (const float*)d_in[7];
    const float* bt   = (const float*)d_in[8];
    const float* ln_g = (const float*)d_in[9];
    const float* ln_b = (const float*)d_in[10];
    const float* Wk   = (const float*)d_in[11];
    const float* bk   = (const float*)d_in[12];
    const float* Wq   = (const float*)d_in[13];
    const float* bq   = (const float*)d_in[14];
    const float* Wv   = (const float*)d_in[15];
    const float* bv   = (const float*)d_in[16];
    const float* Wa   = (const float*)d_in[17];
    const float* ba   = (const float*)d_in[18];
    const float* skip = (const float*)d_in[19];
    const float* a_rel = (const float*)d_in[20];
    const float* m_rel = (const float*)d_in[21];
    const float* p_rel = (const float*)d_in[22];
    float* out = (float*)d_out;

    float* xw    = symaddr(g_xw);
    float* k_op  = symaddr(g_k_op);
    float* q_op  = symaddr(g_q_op);
    float* v_op  = symaddr(g_v_op);
    float* k_m   = symaddr(g_k_m);
    float* q_m   = symaddr(g_q_m);
    float* v_m   = symaddr(g_v_m);
    float* acc_op = symaddr(g_acc_op);
    float* acc_m  = symaddr(g_acc_m);
    int*   cur4  = (int*)symaddr(g_cur4);

    cudaMemcpyAsync(xw, x_op, (size_t)NOP * DD * sizeof(float), cudaMemcpyDeviceToDevice);
    cudaMemsetAsync(cur4, 0, (size_t)4 * NOP * sizeof(int));

    // L1: temporal encoding + CSR degree count
    fused_temporal_count<<<TEMP_BLOCKS + 4 * CNT_BPT, 256>>>(
        delta_t, ei0, ei1, ei2, ei3, Wt, bt, ln_g, ln_b);

    // L2: 6 k/q/v GEMMs (pipelined 3xTF32) + 4 CSR scans
    fused_kqv_scan<<<3 * TILES_ALL + 4, 256>>>(
        xw, x_m, Wk, Wq, Wv, bk, bq, bv,
        k_op, q_op, v_op, k_m, q_m, v_m);

    // L3: relation transforms (tensor core) + CSR fill
    fused_rel_fill<<<REL_TC + 4 * CNT_BPT, 256>>>(a_rel, m_rel, ei0, ei1, ei2, ei3);

    // L4: both gathers
    fused_gather<<<GOP_BLOCKS + NMM, 256>>>(p_rel);

    // L5: both final GEMMs (tensor core)
    gemm_final<<<TILES_ALL, 256>>>(acc_op, acc_m, Wa, ba, xw, x_m, skip, out);
}

// round 13
// speedup vs baseline: 3.1806x; 1.0003x over previous
#include <cuda_runtime.h>
#include <math.h>
#include <stdint.h>

#define NOP 20000
#define NMM 500
#define DD  256
#define HH  8
#define DHD 32
#define TDE 16
#define EE  200000

#define TILES_OP 314   // 157 rowblocks x 2 colblocks
#define TILES_M  8     // 4 x 2
#define TILES_ALL (TILES_OP + TILES_M)

#define TEMP_BLOCKS 782            // ceil(EE/256), 256 edges per block
#define CNT_BPT 782                // count blocks per edge type: ceil(EE/256)
#define RELB_PER_H 313             // ceil(NOP/64) node-blocks per (type<3, head)
#define RELB_OP (RELB_PER_H * HH)  // 2504 per op-src type
#define RELB_M_PER_H 8             // ceil(NMM/64)
#define REL_TC (3 * RELB_OP + RELB_M_PER_H * HH)   // 7576
#define GOP_BLOCKS 2500            // NOP*32/256

// ---------------- scratch ----------------
__device__ float g_xw[NOP * DD];
__device__ float g_k_op[NOP * DD];
__device__ float g_q_op[NOP * DD];
__device__ float g_v_op[NOP * DD];
__device__ float g_k_m[NMM * DD];
__device__ float g_q_m[NMM * DD];
__device__ float g_v_m[NMM * DD];
__device__ float g_KT[3][NOP * DD];
__device__ float g_VT[3][NOP * DD];
__device__ float g_KTm[NMM * DD];
__device__ float g_VTm[NMM * DD];
__device__ float g_acc_op[NOP * DD];
__device__ float g_acc_m[NMM * DD];
__device__ int   g_off4[4][NOP + 1];
__device__ int   g_cur4[4][NOP];
__device__ int   g_esrc4[4][EE];

__device__ __forceinline__ float gelu_exact(float x) {
    return 0.5f * x * (1.0f + erff(x * 0.70710678118654752f));
}

__device__ __forceinline__ void red_add_v4(float* p, float a, float b, float c, float d) {
    asm volatile("red.global.add.v4.f32 [%0], {%1, %2, %3, %4};"
                 :: "l"(p), "f"(a), "f"(b), "f"(c), "f"(d) : "memory");
}

__device__ __forceinline__ uint32_t cvt_tf32(float x) {
    uint32_t r; asm("cvt.rna.tf32.f32 %0, %1;" : "=r"(r) : "f"(x)); return r;
}

__device__ __forceinline__ void mma_tf32(float* c, const uint32_t* a, const uint32_t* b) {
    asm volatile("mma.sync.aligned.m16n8k8.row.col.f32.tf32.tf32.f32 "
                 "{%0,%1,%2,%3}, {%4,%5,%6,%7}, {%8,%9}, {%0,%1,%2,%3};"
                 : "+f"(c[0]), "+f"(c[1]), "+f"(c[2]), "+f"(c[3])
                 : "r"(a[0]), "r"(a[1]), "r"(a[2]), "r"(a[3]),
                   "r"(b[0]), "r"(b[1]));
}

// ---------------- temporal encoding: 256 edges per block, 8 warps x 32 edges ----------------
__device__ void temporal_body(int blk,
                              const float* __restrict__ delta_t,
                              const int* __restrict__ ei_src,
                              const float* __restrict__ Wt,
                              const float* __restrict__ bt,
                              const float* __restrict__ ln_g,
                              const float* __restrict__ ln_b)
{
    __shared__ float Wts[TDE * DD];
    __shared__ float bts[DD], gs[DD], bs[DD];
    __shared__ float tr[8][DD];
    for (int idx = threadIdx.x; idx < DD * TDE; idx += blockDim.x) {
        int j = idx / TDE, i = idx % TDE;
        Wts[i * DD + j] = Wt[idx];
    }
    for (int idx = threadIdx.x; idx < DD; idx += blockDim.x) {
        bts[idx] = bt[idx]; gs[idx] = ln_g[idx]; bs[idx] = ln_b[idx];
    }
    __syncthreads();

    int warp = threadIdx.x >> 5;
    int lane = threadIdx.x & 31;

    float freqs[8];
    #pragma unroll
    for (int m = 0; m < 8; m++)
        freqs[m] = exp2f(-(float)m * (9.965784284662087f / 8.0f));  // 1000^{-m/8}

    #pragma unroll 1
    for (int t = 0; t < 32; t++) {
        int w = blk * 256 + warp * 32 + t;
        if (w >= EE) break;

        float dt = delta_t[w];
        int src = ei_src[w];

        float sn[8], cn[8];
        #pragma unroll
        for (int m = 0; m < 8; m++) sincosf(dt * freqs[m], &sn[m], &cn[m]);

        float pt[8];
        float lsum = 0.0f;
        #pragma unroll
        for (int jj = 0; jj < 8; jj++) {
            int j = lane + jj * 32;
            float s = bts[j];
            #pragma unroll
            for (int m = 0; m < 8; m++)
                s += sn[m] * Wts[(2 * m) * DD + j] + cn[m] * Wts[(2 * m + 1) * DD + j];
            pt[jj] = s;
            lsum += s;
        }
        #pragma unroll
        for (int o = 16; o; o >>= 1) lsum += __shfl_xor_sync(0xffffffffu, lsum, o);
        float mu = lsum * (1.0f / 256.0f);

        float lvar = 0.0f;
        #pragma unroll
        for (int jj = 0; jj < 8; jj++) { float d = pt[jj] - mu; lvar += d * d; }
        #pragma unroll
        for (int o = 16; o; o >>= 1) lvar += __shfl_xor_sync(0xffffffffu, lvar, o);
        float rstd = rsqrtf(lvar * (1.0f / 256.0f) + 1e-5f);

        #pragma unroll
        for (int jj = 0; jj < 8; jj++) {
            int j = lane + jj * 32;
            tr[warp][j] = (pt[jj] - mu) * rstd * gs[j] + bs[j];
        }
        __syncwarp();
        float4 y0 = *(const float4*)&tr[warp][lane * 8];
        float4 y1 = *(const float4*)&tr[warp][lane * 8 + 4];
        float* xp = &g_xw[(size_t)src * DD + lane * 8];
        red_add_v4(xp,     y0.x, y0.y, y0.z, y0.w);
        red_add_v4(xp + 4, y1.x, y1.y, y1.z, y1.w);
        __syncwarp();
    }
}

// ---------------- launch 1: temporal + CSR count ----------------
__global__ void __launch_bounds__(256) fused_temporal_count(
    const float* __restrict__ delta_t,
    const int* __restrict__ e0, const int* __restrict__ e1,
    const int* __restrict__ e2, const int* __restrict__ e3,
    const float* __restrict__ Wt, const float* __restrict__ bt,
    const float* __restrict__ ln_g, const float* __restrict__ ln_b)
{
    int b = blockIdx.x;
    if (b < TEMP_BLOCKS) {
        temporal_body(b, delta_t, e0, Wt, bt, ln_g, ln_b);
    } else {
        int cb = b - TEMP_BLOCKS;
        int ty = cb / CNT_BPT;
        int i = (cb % CNT_BPT) * 256 + threadIdx.x;
        if (i < EE) {
            const int* ei = (ty == 0) ? e0 : (ty == 1) ? e1 : (ty == 2) ? e2 : e3;
            atomicAdd(&g_cur4[ty][ei[EE + i]], 1);
        }
    }
}

// ---------------- tensor-core 3xTF32 GEMM tile: 128x128, K=256, pipelined ----------------
#define SMP 20

__device__ __forceinline__ void split_store(uint32_t* H, uint32_t* L, int idx, float4 v) {
    uint32_t h0 = cvt_tf32(v.x), h1 = cvt_tf32(v.y), h2 = cvt_tf32(v.z), h3 = cvt_tf32(v.w);
    uint32_t l0 = cvt_tf32(v.x - __uint_as_float(h0));
    uint32_t l1 = cvt_tf32(v.y - __uint_as_float(h1));
    uint32_t l2 = cvt_tf32(v.z - __uint_as_float(h2));
    uint32_t l3 = cvt_tf32(v.w - __uint_as_float(h3));
    *(uint4*)&H[idx] = make_uint4(h0, h1, h2, h3);
    *(uint4*)&L[idx] = make_uint4(l0, l1, l2, l3);
}

template <bool FUSE>
__device__ __forceinline__ void gemm_tile_tc(
    const float* __restrict__ A, const float* __restrict__ W,
    const float* __restrict__ bias, float* __restrict__ C, int N,
    const float* __restrict__ xsrc, float sa, int rowBase, int colBase)
{
    __shared__ uint32_t Ah[128 * SMP], Al[128 * SMP];
    __shared__ uint32_t Bh[128 * SMP], Bl[128 * SMP];

    int tid = threadIdx.x;
    int lane = tid & 31;
    int wid = tid >> 5;
    int mwarp = wid >> 2;
    int nwarp = wid & 3;
    int grp  = lane >> 2;
    int tid4 = lane & 3;

    int row0 = tid >> 2, q0 = (tid & 3) * 4;
    int row1 = row0 + 64;
    int gr0 = rowBase + row0, gr1 = rowBase + row1;
    int gc0 = colBase + row0, gc1 = colBase + row1;

    float acc[4][4][4];
    #pragma unroll
    for (int i = 0; i < 4; i++)
        #pragma unroll
        for (int j = 0; j < 4; j++)
            #pragma unroll
            for (int r = 0; r < 4; r++) acc[i][j][r] = 0.0f;

    float4 av0, av1, bv0, bv1;
    auto ldg = [&](int kt) {
        av0 = make_float4(0.f, 0.f, 0.f, 0.f);
        av1 = make_float4(0.f, 0.f, 0.f, 0.f);
        if (gr0 < N) av0 = *(const float4*)(A + (size_t)gr0 * 256 + kt + q0);
        if (gr1 < N) av1 = *(const float4*)(A + (size_t)gr1 * 256 + kt + q0);
        if (FUSE) {
            av0.x = gelu_exact(av0.x); av0.y = gelu_exact(av0.y);
            av0.z = gelu_exact(av0.z); av0.w = gelu_exact(av0.w);
            av1.x = gelu_exact(av1.x); av1.y = gelu_exact(av1.y);
            av1.z = gelu_exact(av1.z); av1.w = gelu_exact(av1.w);
        }
        bv0 = *(const float4*)(W + (size_t)gc0 * 256 + kt + q0);
        bv1 = *(const float4*)(W + (size_t)gc1 * 256 + kt + q0);
    };
    auto sts = [&]() {
        split_store(Ah, Al, row0 * SMP + q0, av0);
        split_store(Ah, Al, row1 * SMP + q0, av1);
        split_store(Bh, Bl, row0 * SMP + q0, bv0);
        split_store(Bh, Bl, row1 * SMP + q0, bv1);
    };

    ldg(0);
    sts();
    __syncthreads();

    for (int it = 0; it < 16; it++) {
        if (it < 15) ldg((it + 1) * 16);   // prefetch hides under mma

        #pragma unroll
        for (int s = 0; s < 2; s++) {
            int kb = s * 8 + tid4;
            uint32_t ah[4][4], al[4][4];
            #pragma unroll
            for (int mt = 0; mt < 4; mt++) {
                int base = (mwarp * 64 + mt * 16 + grp) * SMP + kb;
                ah[mt][0] = Ah[base];            al[mt][0] = Al[base];
                ah[mt][1] = Ah[base + 8 * SMP];  al[mt][1] = Al[base + 8 * SMP];
                ah[mt][2] = Ah[base + 4];        al[mt][2] = Al[base + 4];
                ah[mt][3] = Ah[base + 8 * SMP + 4]; al[mt][3] = Al[base + 8 * SMP + 4];
            }
            uint32_t bh[4][2], bl[4][2];
            #pragma unroll
            for (int nt = 0; nt < 4; nt++) {
                int base = (nwarp * 32 + nt * 8 + grp) * SMP + kb;
                bh[nt][0] = Bh[base];     bl[nt][0] = Bl[base];
                bh[nt][1] = Bh[base + 4]; bl[nt][1] = Bl[base + 4];
            }
            #pragma unroll
            for (int mt = 0; mt < 4; mt++)
                #pragma unroll
                for (int nt = 0; nt < 4; nt++) {
                    mma_tf32(acc[mt][nt], ah[mt], bh[nt]);
                    mma_tf32(acc[mt][nt], ah[mt], bl[nt]);
                    mma_tf32(acc[mt][nt], al[mt], bh[nt]);
                }
        }
        __syncthreads();
        if (it < 15) {
            sts();
            __syncthreads();
        }
    }

    #pragma unroll
    for (int mt = 0; mt < 4; mt++) {
        int r0g = rowBase + mwarp * 64 + mt * 16 + grp;
        int r1g = r0g + 8;
        #pragma unroll
        for (int nt = 0; nt < 4; nt++) {
            int c = colBase + nwarp * 32 + nt * 8 + tid4 * 2;
            float2 bi = *(const float2*)(bias + c);
            if (r0g < N) {
                float o0 = acc[mt][nt][0] + bi.x;
                float o1 = acc[mt][nt][1] + bi.y;
                if (FUSE) {
                    float2 xs = *(const float2*)(xsrc + (size_t)r0g * 256 + c);
                    o0 = sa * o0 + (1.0f - sa) * xs.x;
                    o1 = sa * o1 + (1.0f - sa) * xs.y;
                }
                *(float2*)(C + (size_t)r0g * 256 + c) = make_float2(o0, o1);
            }
            if (r1g < N) {
                float o2 = acc[mt][nt][2] + bi.x;
                float o3 = acc[mt][nt][3] + bi.y;
                if (FUSE) {
                    float2 xs = *(const float2*)(xsrc + (size_t)r1g * 256 + c);
                    o2 = sa * o2 + (1.0f - sa) * xs.x;
                    o3 = sa * o3 + (1.0f - sa) * xs.y;
                }
                *(float2*)(C + (size_t)r1g * 256 + c) = make_float2(o2, o3);
            }
        }
    }
}

// 256-thread exclusive scan of g_cur4[ty] -> g_off4[ty]; cur := offset
__device__ void csr_scan_body(int ty) {
    int Nd = (ty == 2) ? NMM : NOP;
    __shared__ int sp[256];
    int tid = threadIdx.x;
    int chunk = (Nd + 255) / 256;
    int beg = tid * chunk;
    int end = beg + chunk; if (end > Nd) end = Nd;
    int s = 0;
    for (int i = beg; i < end; i++) s += g_cur4[ty][i];
    sp[tid] = s;
    __syncthreads();
    #pragma unroll
    for (int o = 1; o < 256; o <<= 1) {
        int v = (tid >= o) ? sp[tid - o] : 0;
        __syncthreads();
        sp[tid] += v;
        __syncthreads();
    }
    int base = (tid == 0) ? 0 : sp[tid - 1];
    for (int i = beg; i < end; i++) {
        int d = g_cur4[ty][i];
        g_off4[ty][i] = base;
        g_cur4[ty][i] = base;
        base += d;
    }
    if (tid == 255) g_off4[ty][Nd] = sp[255];
}

// ---------------- launch 2: 6 k/q/v GEMMs + 4 CSR scans ----------------
__global__ void __launch_bounds__(256) fused_kqv_scan(
    const float* __restrict__ Aop, const float* __restrict__ Am,
    const float* __restrict__ Wk, const float* __restrict__ Wq, const float* __restrict__ Wv,
    const float* __restrict__ bk, const float* __restrict__ bq, const float* __restrict__ bv,
    float* __restrict__ kop, float* __restrict__ qop, float* __restrict__ vop,
    float* __restrict__ km,  float* __restrict__ qm,  float* __restrict__ vm)
{
    int b = blockIdx.x;
    if (b < 3 * TILES_ALL) {
        int z = b / TILES_ALL;
        int t = b % TILES_ALL;
        bool isM = t >= TILES_OP;
        int tt = isM ? t - TILES_OP : t;
        int rowBase = (tt >> 1) * 128;
        int colBase = (tt & 1) * 128;

        const float* A = isM ? Am : Aop;
        int N = isM ? NMM : NOP;
        const float* W = (z == 0 ? Wk : z == 1 ? Wq : Wv) + (isM ? DD * DD : 0);
        const float* bb = (z == 0 ? bk : z == 1 ? bq : bv) + (isM ? DD : 0);
        float* C = isM ? (z == 0 ? km : z == 1 ? qm : vm)
                       : (z == 0 ? kop : z == 1 ? qop : vop);
        gemm_tile_tc<false>(A, W, bb, C, N, nullptr, 0.0f, rowBase, colBase);
    } else {
        csr_scan_body(b - 3 * TILES_ALL);
    }
}

// ---------------- tensor-core rel transform: [64 x 32] @ [32 x 32] per (e,h) block ----------------
// K̃[n,f] = sum_d k[n,h*32+d] * a_rel[e,h,d,f]  (B loaded transposed: Bsmem[f][d])
__device__ void rel_body_tc(int e, int h, int xb,
                            const float* __restrict__ arel,
                            const float* __restrict__ mrel)
{
    int N = (e == 3) ? NMM : NOP;
    int nBase = xb * 64;
    if (nBase >= N) return;

    const float* ktab = (e == 3) ? g_k_m : g_k_op;
    const float* vtab = (e == 3) ? g_v_m : g_v_op;
    float* KT = (e == 3) ? g_KTm : g_KT[e];
    float* VT = (e == 3) ? g_VTm : g_VT[e];

    __shared__ uint32_t Ah[64 * 36], Al[64 * 36];
    __shared__ uint32_t Bah[32 * 36], Bal[32 * 36], Bmh[32 * 36], Bml[32 * 36];

    int tid = threadIdx.x, lane = tid & 31, wid = tid >> 5;
    int grp = lane >> 2, tid4 = lane & 3;
    int mt = wid & 3;             // m-tile (16 rows) within 64
    int ntbase = (wid >> 2) * 2;  // 2 n-tiles of 8 per warp

    // load both relation matrices (transposed) with hi/lo split
    for (int i = tid; i < 1024; i += 256) {
        int d = i >> 5, f = i & 31;
        float va = arel[((size_t)(e * HH + h)) * 1024 + i];
        float vm = mrel[((size_t)(e * HH + h)) * 1024 + i];
        uint32_t hh = cvt_tf32(va);
        Bah[f * 36 + d] = hh;
        Bal[f * 36 + d] = cvt_tf32(va - __uint_as_float(hh));
        hh = cvt_tf32(vm);
        Bmh[f * 36 + d] = hh;
        Bml[f * 36 + d] = cvt_tf32(vm - __uint_as_float(hh));
    }

    #pragma unroll
    for (int phase = 0; phase < 2; phase++) {
        const float* xt = phase ? vtab : ktab;
        __syncthreads();   // phase0: B stores done; phase1: prior mma reads done before A overwrite
        for (int q = tid; q < 512; q += 256) {
            int r = q >> 3, c4 = (q & 7) * 4;
            float4 v = make_float4(0.f, 0.f, 0.f, 0.f);
            if (nBase + r < N)
                v = *(const float4*)(xt + (size_t)(nBase + r) * 256 + h * 32 + c4);
            uint32_t h0 = cvt_tf32(v.x), h1 = cvt_tf32(v.y), h2 = cvt_tf32(v.z), h3 = cvt_tf32(v.w);
            int idx = r * 36 + c4;
            Ah[idx] = h0; Ah[idx + 1] = h1; Ah[idx + 2] = h2; Ah[idx + 3] = h3;
            Al[idx]     = cvt_tf32(v.x - __uint_as_float(h0));
            Al[idx + 1] = cvt_tf32(v.y - __uint_as_float(h1));
            Al[idx + 2] = cvt_tf32(v.z - __uint_as_float(h2));
            Al[idx + 3] = cvt_tf32(v.w - __uint_as_float(h3));
        }
        __syncthreads();

        const uint32_t* Bh = phase ? Bmh : Bah;
        const uint32_t* Bl = phase ? Bml : Bal;
        float acc[2][4];
        #pragma unroll
        for (int j = 0; j < 2; j++)
            #pragma unroll
            for (int r = 0; r < 4; r++) acc[j][r] = 0.0f;

        #pragma unroll
        for (int kc = 0; kc < 4; kc++) {
            int kb = kc * 8 + tid4;
            int ab = (mt * 16 + grp) * 36 + kb;
            uint32_t ah[4] = {Ah[ab], Ah[ab + 8 * 36], Ah[ab + 4], Ah[ab + 8 * 36 + 4]};
            uint32_t al[4] = {Al[ab], Al[ab + 8 * 36], Al[ab + 4], Al[ab + 8 * 36 + 4]};
            #pragma unroll
            for (int j = 0; j < 2; j++) {
                int bb = ((ntbase + j) * 8 + grp) * 36 + kb;
                uint32_t bh[2] = {Bh[bb], Bh[bb + 4]};
                uint32_t bl[2] = {Bl[bb], Bl[bb + 4]};
                mma_tf32(acc[j], ah, bh);
                mma_tf32(acc[j], ah, bl);
                mma_tf32(acc[j], al, bh);
            }
        }

        float* OUT = phase ? VT : KT;
        int r0 = nBase + mt * 16 + grp;
        int r1 = r0 + 8;
        #pragma unroll
        for (int j = 0; j < 2; j++) {
            int c = (ntbase + j) * 8 + tid4 * 2;
            if (r0 < N)
                *(float2*)(OUT + (size_t)r0 * 256 + h * 32 + c) = make_float2(acc[j][0], acc[j][1]);
            if (r1 < N)
                *(float2*)(OUT + (size_t)r1 * 256 + h * 32 + c) = make_float2(acc[j][2], acc[j][3]);
        }
    }
}

// ---------------- launch 3: rel transforms (TC) + CSR fill ----------------
__global__ void __launch_bounds__(256) fused_rel_fill(
    const float* __restrict__ arel, const float* __restrict__ mrel,
    const int* __restrict__ e0, const int* __restrict__ e1,
    const int* __restrict__ e2, const int* __restrict__ e3)
{
    int b = blockIdx.x;
    if (b < 3 * RELB_OP) {
        int e = b / RELB_OP;
        int rem = b % RELB_OP;
        int h = rem / RELB_PER_H;
        int xb = rem % RELB_PER_H;
        rel_body_tc(e, h, xb, arel, mrel);
    } else if (b < REL_TC) {
        int b2 = b - 3 * RELB_OP;
        int h = b2 / RELB_M_PER_H;
        int xb = b2 % RELB_M_PER_H;
        rel_body_tc(3, h, xb, arel, mrel);
    } else {
        int cb = b - REL_TC;
        int ty = cb / CNT_BPT;
        int i = (cb % CNT_BPT) * 256 + threadIdx.x;
        if (i < EE) {
            const int* ei = (ty == 0) ? e0 : (ty == 1) ? e1 : (ty == 2) ? e2 : e3;
            int dst = ei[EE + i];
            int src = ei[i];
            int pos = atomicAdd(&g_cur4[ty][dst], 1);
            g_esrc4[ty][pos] = src;
        }
    }
}

// ---------------- gather bodies ----------------
__device__ void gather_op_body(int b, const float* __restrict__ prel)
{
    int w = b * 8 + (threadIdx.x >> 5);
    int lane = threadIdx.x & 31;
    if (w >= NOP) return;

    const float4* qp = (const float4*)(g_q_op + (size_t)w * 256);
    float4 q0 = qp[lane * 2], q1 = qp[lane * 2 + 1];
    int h = lane >> 2;

    float out[8] = {0.f, 0.f, 0.f, 0.f, 0.f, 0.f, 0.f, 0.f};

    #pragma unroll
    for (int pass = 0; pass < 3; pass++) {
        int e = (pass == 2) ? 3 : pass;
        const float* KT = (pass == 2) ? g_KTm : g_KT[e];
        const float* VT = (pass == 2) ? g_VTm : g_VT[e];
        float ps = prel[e * HH + h] * 0.17677669529663687f;   // 1/sqrt(32)

        int beg = g_off4[e][w], end = g_off4[e][w + 1];
        float num[8] = {0.f, 0.f, 0.f, 0.f, 0.f, 0.f, 0.f, 0.f};
        float den = 0.0f;
        #pragma unroll 2
        for (int j = beg; j < end; j++) {
            int src = g_esrc4[e][j];
            const float4* kp = (const float4*)(KT + (size_t)src * 256);
            const float4* vp = (const float4*)(VT + (size_t)src * 256);
            float4 k0 = kp[lane * 2], k1 = kp[lane * 2 + 1];
            float4 v0 = vp[lane * 2], v1 = vp[lane * 2 + 1];
            float s = q0.x * k0.x + q0.y * k0.y + q0.z * k0.z + q0.w * k0.w
                    + q1.x * k1.x + q1.y * k1.y + q1.z * k1.z + q1.w * k1.w;
            s += __shfl_xor_sync(0xffffffffu, s, 1);
            s += __shfl_xor_sync(0xffffffffu, s, 2);
            float ev = expf(s * ps);
            den += ev;
            num[0] += ev * v0.x; num[1] += ev * v0.y; num[2] += ev * v0.z; num[3] += ev * v0.w;
            num[4] += ev * v1.x; num[5] += ev * v1.y; num[6] += ev * v1.z; num[7] += ev * v1.w;
        }
        float inv = (den > 0.f) ? 1.0f / den : 0.0f;
        #pragma unroll
        for (int i = 0; i < 8; i++) out[i] += num[i] * inv;
    }

    float* ap = g_acc_op + (size_t)w * 256 + lane * 8;
    *(float4*)(ap)     = make_float4(out[0], out[1], out[2], out[3]);
    *(float4*)(ap + 4) = make_float4(out[4], out[5], out[6], out[7]);
}

__device__ void gather_m_body(int n, const float* __restrict__ prel)
{
    __shared__ float snum[8][256];
    __shared__ float sden[8][8];
    int warp = threadIdx.x >> 5, lane = threadIdx.x & 31;
    int h = lane >> 2;
    int beg = g_off4[2][n], end = g_off4[2][n + 1];

    const float4* qp = (const float4*)(g_q_m + (size_t)n * 256);
    float4 q0 = qp[lane * 2], q1 = qp[lane * 2 + 1];
    float ps = prel[2 * HH + h] * 0.17677669529663687f;

    float num[8] = {0.f, 0.f, 0.f, 0.f, 0.f, 0.f, 0.f, 0.f};
    float den = 0.0f;

    for (int j = beg + warp; j < end; j += 8) {
        int src = g_esrc4[2][j];
        const float4* kp = (const float4*)(g_KT[2] + (size_t)src * 256);
        const float4* vp = (const float4*)(g_VT[2] + (size_t)src * 256);
        float4 k0 = kp[lane * 2], k1 = kp[lane * 2 + 1];
        float4 v0 = vp[lane * 2], v1 = vp[lane * 2 + 1];
        float s = q0.x * k0.x + q0.y * k0.y + q0.z * k0.z + q0.w * k0.w
                + q1.x * k1.x + q1.y * k1.y + q1.z * k1.z + q1.w * k1.w;
        s += __shfl_xor_sync(0xffffffffu, s, 1);
        s += __shfl_xor_sync(0xffffffffu, s, 2);
        float ev = expf(s * ps);
        den += ev;
        num[0] += ev * v0.x; num[1] += ev * v0.y; num[2] += ev * v0.z; num[3] += ev * v0.w;
        num[4] += ev * v1.x; num[5] += ev * v1.y; num[6] += ev * v1.z; num[7] += ev * v1.w;
    }
    #pragma unroll
    for (int i = 0; i < 8; i += 4)
        *(float4*)&snum[warp][lane * 8 + i] = make_float4(num[i], num[i+1], num[i+2], num[i+3]);
    if ((lane & 3) == 0) sden[warp][h] = den;
    __syncthreads();

    {
        int c = threadIdx.x;
        float tot = 0.0f;
        #pragma unroll
        for (int ww = 0; ww < 8; ww++) tot += snum[ww][c];
        int hh = c >> 5;
        float d = 0.0f;
        #pragma unroll
        for (int ww = 0; ww < 8; ww++) d += sden[ww][hh];
        g_acc_m[(size_t)n * 256 + c] = (d > 0.f) ? tot / d : 0.0f;
    }
}

// ---------------- launch 4: both gathers ----------------
__global__ void __launch_bounds__(256) fused_gather(const float* __restrict__ prel)
{
    int b = blockIdx.x;
    if (b < GOP_BLOCKS) gather_op_body(b, prel);
    else                gather_m_body(b - GOP_BLOCKS, prel);
}

// ---------------- launch 5: both final FUSE GEMMs ----------------
__global__ void __launch_bounds__(256) gemm_final(
    const float* __restrict__ accop, const float* __restrict__ accm,
    const float* __restrict__ Wa, const float* __restrict__ ba,
    const float* __restrict__ xop, const float* __restrict__ xm,
    const float* __restrict__ skipv, float* __restrict__ out)
{
    int t = blockIdx.x;
    bool isM = t >= TILES_OP;
    int tt = isM ? t - TILES_OP : t;
    int rowBase = (tt >> 1) * 128;
    int colBase = (tt & 1) * 128;

    const float* A = isM ? accm : accop;
    int N = isM ? NMM : NOP;
    const float* W = Wa + (isM ? DD * DD : 0);
    const float* b = ba + (isM ? DD : 0);
    const float* xs = isM ? xm : xop;
    float* C = out + (isM ? (size_t)NOP * DD : 0);
    float sa = 1.0f / (1.0f + expf(-skipv[isM ? 1 : 0]));

    gemm_tile_tc<true>(A, W, b, C, N, xs, sa, rowBase, colBase);
}

// ---------------- host side ----------------
static float* symaddr(const void* sym) {
    void* p = nullptr;
    cudaGetSymbolAddress(&p, sym);
    return (float*)p;
}

extern "C" void kernel_launch(void* const* d_in, const int* in_sizes, int n_in,
                              void* d_out, int out_size)
{
    const float* x_op    = (const float*)d_in[0];
    const float* x_m     = (const float*)d_in[1];
    const float* delta_t = (const float*)d_in[2];
    const int*   ei0 = (const int*)d_in[3];
    const int*   ei1 = (const int*)d_in[4];
    const int*   ei2 = (const int*)d_in[5];
    const int*   ei3 = (const int*)d_in[6];
    const float* Wt   = (const float*)d_in[7];
    const float* bt   = (const float*)d_in[8];
    const float* ln_g = (const float*)d_in[9];
    const float* ln_b = (const float*)d_in[10];
    const float* Wk   = (const float*)d_in[11];
    const float* bk   = (const float*)d_in[12];
    const float* Wq   = (const float*)d_in[13];
    const float* bq   = (const float*)d_in[14];
    const float* Wv   = (const float*)d_in[15];
    const float* bv   = (const float*)d_in[16];
    const float* Wa   = (const float*)d_in[17];
    const float* ba   = (const float*)d_in[18];
    const float* skip = (const float*)d_in[19];
    const float* a_rel = (const float*)d_in[20];
    const float* m_rel = (const float*)d_in[21];
    const float* p_rel = (const float*)d_in[22];
    float* out = (float*)d_out;

    float* xw    = symaddr(g_xw);
    float* k_op  = symaddr(g_k_op);
    float* q_op  = symaddr(g_q_op);
    float* v_op  = symaddr(g_v_op);
    float* k_m   = symaddr(g_k_m);
    float* q_m   = symaddr(g_q_m);
    float* v_m   = symaddr(g_v_m);
    float* acc_op = symaddr(g_acc_op);
    float* acc_m  = symaddr(g_acc_m);
    int*   cur4  = (int*)symaddr(g_cur4);

    cudaMemcpyAsync(xw, x_op, (size_t)NOP * DD * sizeof(float), cudaMemcpyDeviceToDevice);
    cudaMemsetAsync(cur4, 0, (size_t)4 * NOP * sizeof(int));

    // L1: temporal encoding + CSR degree count
    fused_temporal_count<<<TEMP_BLOCKS + 4 * CNT_BPT, 256>>>(
        delta_t, ei0, ei1, ei2, ei3, Wt, bt, ln_g, ln_b);

    // L2: 6 k/q/v GEMMs (pipelined 3xTF32) + 4 CSR scans
    fused_kqv_scan<<<3 * TILES_ALL + 4, 256>>>(
        xw, x_m, Wk, Wq, Wv, bk, bq, bv,
        k_op, q_op, v_op, k_m, q_m, v_m);

    // L3: relation transforms (tensor core) + CSR fill
    fused_rel_fill<<<REL_TC + 4 * CNT_BPT, 256>>>(a_rel, m_rel, ei0, ei1, ei2, ei3);

    // L4: both gathers
    fused_gather<<<GOP_BLOCKS + NMM, 256>>>(p_rel);

    // L5: both final GEMMs (tensor core)
    gemm_final<<<TILES_ALL, 256>>>(acc_op, acc_m, Wa, ba, xw, x_m, skip, out);
}